// round 1
// baseline (speedup 1.0000x reference)
#include <cuda_runtime.h>
#include <cstdint>

// Problem constants
#define BN   8
#define CIN  3
#define COUT 3
#define WIDC 16
#define M1C  8
#define M2C  8
#define HH   256
#define WW   256
#define NPIX 65536      // HH*WW
#define TWO_PI 6.28318530717958647692f

// ---------------- device scratch (allocation-free: static __device__ globals) ----
__device__ float  g_v [BN*WIDC*NPIX];          // fc0 output [b][c][h][w]
__device__ float  g_vn[BN*WIDC*NPIX];          // inorm(v)
__device__ float2 g_cbuf [BN*WIDC*NPIX];       // row-FFT intermediate / ifft intermediate
__device__ float2 g_alpha[BN*WIDC*NPIX];       // FFT2(vn) [b][i][o][x]
__device__ float2 g_out1 [BN*WIDC*NPIX];       // mixed spectrum [b][k][o][x]
__device__ float2 g_G [WIDC*WIDC*NPIX];        // transfer kernel [i][k][o][x]
__device__ float  g_x1[BN*WIDC*NPIX];          // ifft2(out1).real
__device__ float  g_x2[BN*WIDC*NPIX];          // transient part
__device__ float  g_u [BN*NPIX*WIDC];          // pre-MLP activations [b][hw][c]
__device__ float2 g_A1[WIDC*WIDC*M1C*HH];      // [i][k][p][o]
__device__ float2 g_A2[WIDC*WIDC*M2C*WW];      // [i][k][q][x]
__device__ float2 g_E1[WIDC*WIDC*M1C*HH];      // exp(p1*ty) [i][k][p][z]
__device__ float2 g_E2[WIDC*WIDC*M2C*WW];      // exp(p2*tx) [i][k][q][x]
__device__ float2 g_T [WIDC*WIDC*M2C*HH];      // [i][k][q][o]
__device__ float2 g_D [BN*WIDC*WIDC*M1C*WW];   // [b][i][k][p][x]
__device__ float2 g_J [BN*WIDC*WIDC*M1C*M2C];  // [b][i][k][p][q]
__device__ float2 g_o2[BN*WIDC*M1C*M2C];       // out2 [b][k][p][q]
__device__ float2 g_U [BN*WIDC*WIDC*M2C*HH];   // [n][c0][c1][q][z]
__device__ float2 g_st1[BN*WIDC];              // (mu, rstd) of v
__device__ float2 g_st2[BN*WIDC];              // (mu, rstd) of x1+x2

// ---------------- helpers ----------------
__device__ __forceinline__ float2 cmulf(float2 a, float2 b) {
    return make_float2(fmaf(a.x, b.x, -a.y * b.y), fmaf(a.x, b.y, a.y * b.x));
}
__device__ __forceinline__ void cacc(float2& a, float2 b, float2 c) {
    // a += b*c
    a.x = fmaf(b.x, c.x, a.x); a.x = fmaf(-b.y, c.y, a.x);
    a.y = fmaf(b.x, c.y, a.y); a.y = fmaf(b.y, c.x, a.y);
}

// 256-point radix-2 DIT FFT in shared memory. 128 participating "t" lanes per
// transform; data at s[idx*STRIDE]. dir = -1 forward, +1 inverse (unnormalized).
template<int STRIDE>
__device__ void fft256_sh(float2* s, int t, float dir) {
    // bit-reversal permutation (each unordered pair swapped by exactly one lane)
    for (int i = t; i < 256; i += 128) {
        int j = (int)(__brev((unsigned)i) >> 24);
        if (j > i) { float2 tmp = s[i*STRIDE]; s[i*STRIDE] = s[j*STRIDE]; s[j*STRIDE] = tmp; }
    }
    __syncthreads();
    #pragma unroll
    for (int ls = 1; ls <= 8; ls++) {
        const int len = 1 << ls, half = len >> 1;
        const int g = t >> (ls - 1);
        const int p = t & (half - 1);
        const int i1 = (g << ls) + p;
        const int i2 = i1 + half;
        float ang = dir * TWO_PI * (float)p / (float)len;
        float sn, cs; __sincosf(ang, &sn, &cs);
        float2 a = s[i1*STRIDE];
        float2 tb = cmulf(make_float2(cs, sn), s[i2*STRIDE]);
        s[i1*STRIDE] = make_float2(a.x + tb.x, a.y + tb.y);
        s[i2*STRIDE] = make_float2(a.x - tb.x, a.y - tb.y);
        __syncthreads();
    }
}

// ---------------- stage kernels ----------------

// v[b][c][h][w] = concat(x, gridx, gridy) @ fc0_w + fc0_b
__global__ void k_fc0(const float* __restrict__ x, const float* __restrict__ fw,
                      const float* __restrict__ fb) {
    int idx = blockIdx.x * 256 + threadIdx.x;      // b*NPIX
    int b = idx >> 16, hw = idx & 65535;
    int hh = hw >> 8, ww = hw & 255;
    float xi0 = x[(size_t)(b*3 + 0)*NPIX + hw];
    float xi1 = x[(size_t)(b*3 + 1)*NPIX + hw];
    float xi2 = x[(size_t)(b*3 + 2)*NPIX + hw];
    float gx = (float)hh * (1.0f/255.0f);
    float gy = (float)ww * (1.0f/255.0f);
    #pragma unroll
    for (int c = 0; c < 16; c++) {
        float val = fb[c];
        val = fmaf(xi0, fw[c],      val);
        val = fmaf(xi1, fw[16 + c], val);
        val = fmaf(xi2, fw[32 + c], val);
        val = fmaf(gx,  fw[48 + c], val);
        val = fmaf(gy,  fw[64 + c], val);
        g_v[(((size_t)(b*16 + c)) << 16) + hw] = val;
    }
}

// instance-norm statistics over the 65536-pixel slice of (a [+ b2])
__device__ void stats_impl(const float* a, const float* b2, float2* st) {
    int bc = blockIdx.x;
    const float* p  = a + ((size_t)bc << 16);
    const float* p2 = b2 ? (b2 + ((size_t)bc << 16)) : nullptr;
    double s = 0.0, s2 = 0.0;
    for (int i = threadIdx.x; i < NPIX; i += 256) {
        float v = p[i];
        if (p2) v += p2[i];
        s += (double)v; s2 += (double)v * (double)v;
    }
    __shared__ double sh[256], sh2[256];
    sh[threadIdx.x] = s; sh2[threadIdx.x] = s2;
    __syncthreads();
    for (int off = 128; off; off >>= 1) {
        if (threadIdx.x < off) { sh[threadIdx.x] += sh[threadIdx.x+off]; sh2[threadIdx.x] += sh2[threadIdx.x+off]; }
        __syncthreads();
    }
    if (threadIdx.x == 0) {
        double mu  = sh[0]  / (double)NPIX;
        double var = sh2[0] / (double)NPIX - mu * mu;
        st[bc] = make_float2((float)mu, (float)(1.0 / sqrt(var + 1e-5)));
    }
}
__global__ void k_stats1() { stats_impl(g_v, nullptr, g_st1); }
__global__ void k_stats2() { stats_impl(g_x1, g_x2, g_st2); }

__global__ void k_norm1() {
    int idx = blockIdx.x * 256 + threadIdx.x;
    float2 st = g_st1[idx >> 16];
    g_vn[idx] = (g_v[idx] - st.x) * st.y;
}

// FFT along w (real input), one row per block
__global__ void k_fft_row_fwd() {
    __shared__ float2 s[256];
    size_t row = blockIdx.x;
    int t = threadIdx.x;
    const float* rp = g_vn + row * 256;
    s[t]       = make_float2(rp[t],       0.0f);
    s[t + 128] = make_float2(rp[t + 128], 0.0f);
    __syncthreads();
    fft256_sh<1>(s, t, -1.0f);
    float2* op = g_cbuf + row * 256;
    op[t] = s[t]; op[t + 128] = s[t + 128];
}

// FFT along h for 4 adjacent x-columns per block (full 32B sectors)
__device__ void fftcol_impl(const float2* __restrict__ in, float2* __restrict__ out,
                            float dir, float scale) {
    __shared__ float2 s[256 * 4];
    int bc = blockIdx.x >> 6;
    int x0 = (blockIdx.x & 63) << 2;
    int t = threadIdx.x;        // 0..511
    int xl = t & 3, tt = t >> 2;
    const float2* base = in + (size_t)bc * NPIX + x0 + xl;
    s[tt*4 + xl]         = base[(size_t)tt * 256];
    s[(tt + 128)*4 + xl] = base[(size_t)(tt + 128) * 256];
    __syncthreads();
    fft256_sh<4>(s + xl, tt, dir);
    float2* ob = out + (size_t)bc * NPIX + x0 + xl;
    float2 r0 = s[tt*4 + xl], r1 = s[(tt + 128)*4 + xl];
    ob[(size_t)tt * 256]         = make_float2(r0.x * scale, r0.y * scale);
    ob[(size_t)(tt + 128) * 256] = make_float2(r1.x * scale, r1.y * scale);
}
__global__ void k_fft_col_fwd() { fftcol_impl(g_cbuf, g_alpha, -1.0f, 1.0f); }
__global__ void k_fft_col_inv() { fftcol_impl(g_out1, g_cbuf,  1.0f, 1.0f/256.0f); }

// inverse FFT along w, take real part
__global__ void k_fft_row_inv_real() {
    __shared__ float2 s[256];
    size_t row = blockIdx.x;
    int t = threadIdx.x;
    const float2* rp = g_cbuf + row * 256;
    s[t] = rp[t]; s[t + 128] = rp[t + 128];
    __syncthreads();
    fft256_sh<1>(s, t, 1.0f);
    g_x1[row * 256 + t]       = s[t].x       * (1.0f/256.0f);
    g_x1[row * 256 + t + 128] = s[t + 128].x * (1.0f/256.0f);
}

// A1/A2/E1/E2 precompute: one thread per (i,k,m,t)
__global__ void k_small(const float2* __restrict__ p1, const float2* __restrict__ p2,
                        const float* __restrict__ tx, const float* __restrict__ ty) {
    int idx = blockIdx.x * 256 + threadIdx.x;   // 524288
    int t  = idx & 255;
    int m  = (idx >> 8) & 7;
    int ik = idx >> 11;                          // 0..255
    float dty = ty[1] - ty[0];
    float dtx = tx[1] - tx[0];
    int fo = (t < 128) ? t : (t - 256);          // fftfreq ordering
    float L1 = TWO_PI * (float)fo / (256.0f * dty);
    float L2 = TWO_PI * (float)fo / (256.0f * dtx);
    float2 pv1 = p1[ik*8 + m];
    float2 pv2 = p2[ik*8 + m];
    { float ar = -pv1.x, ai = L1 - pv1.y; float d = 1.0f/(ar*ar + ai*ai);
      g_A1[idx] = make_float2(ar*d, -ai*d); }
    { float ar = -pv2.x, ai = L2 - pv2.y; float d = 1.0f/(ar*ar + ai*ai);
      g_A2[idx] = make_float2(ar*d, -ai*d); }
    { float tv = ty[t]; float e = __expf(pv1.x*tv); float sn, cs; __sincosf(pv1.y*tv, &sn, &cs);
      g_E1[idx] = make_float2(e*cs, e*sn); }
    { float tv = tx[t]; float e = __expf(pv2.x*tv); float sn, cs; __sincosf(pv2.y*tv, &sn, &cs);
      g_E2[idx] = make_float2(e*cs, e*sn); }
}

// T[i][k][q][o] = sum_p res[i][k][p][q] * A1[i][k][p][o]
__global__ void k_T(const float2* __restrict__ res) {
    int idx = blockIdx.x * 256 + threadIdx.x;   // 524288
    int o = idx & 255;
    int q = (idx >> 8) & 7;
    int ik = idx >> 11;
    float2 acc = make_float2(0.f, 0.f);
    #pragma unroll
    for (int p = 0; p < 8; p++)
        cacc(acc, res[(ik*8 + p)*8 + q], g_A1[(ik*8 + p)*256 + o]);
    g_T[idx] = acc;
}

// G[i][k][o][x] = sum_q T[i][k][q][o] * A2[i][k][q][x]
__global__ void k_G() {
    int iko = blockIdx.x;        // 65536
    int o = iko & 255, ik = iko >> 8;
    int x = threadIdx.x;
    float2 acc = make_float2(0.f, 0.f);
    #pragma unroll
    for (int q = 0; q < 8; q++)
        cacc(acc, g_T[(ik*8 + q)*256 + o], g_A2[(ik*8 + q)*256 + x]);
    g_G[(((size_t)ik) << 16) + (o << 8) + x] = acc;
}

// out1[b][k][f] = sum_i alpha[b][i][f] * G[i][k][f]   (f-tile of 32 per block)
__global__ void k_mix() {
    __shared__ float2 as_[8][16][32];
    int f0 = blockIdx.x * 32;
    int t = threadIdx.x;            // 256
    for (int idx = t; idx < 4096; idx += 256) {
        int fl = idx & 31, i = (idx >> 5) & 15, b2 = idx >> 9;
        as_[b2][i][fl] = g_alpha[(((size_t)(b2*16 + i)) << 16) + f0 + fl];
    }
    __syncthreads();
    int b = t >> 5, fl = t & 31;
    for (int k = 0; k < 16; k++) {
        float2 acc = make_float2(0.f, 0.f);
        #pragma unroll
        for (int i = 0; i < 16; i++)
            cacc(acc, as_[b][i][fl], g_G[(((size_t)(i*16 + k)) << 16) + f0 + fl]);
        g_out1[(((size_t)(b*16 + k)) << 16) + f0 + fl] = acc;
    }
}

// D[b][i][k][p][x] = sum_o alpha[b][i][o][x] * A1[i][k][p][o]
__global__ void k_D() {
    __shared__ float2 A1s[8 * 256];
    int blk = blockIdx.x;           // 2048 = ((b*16+i)*16+k)
    int k = blk & 15, i = (blk >> 4) & 15, b = blk >> 8;
    int t = threadIdx.x;            // x
    for (int idx = t; idx < 2048; idx += 256)
        A1s[idx] = g_A1[((i*16 + k) << 11) + idx];
    __syncthreads();
    float2 acc[8];
    #pragma unroll
    for (int p = 0; p < 8; p++) acc[p] = make_float2(0.f, 0.f);
    const float2* ap = g_alpha + (((size_t)(b*16 + i)) << 16);
    for (int o = 0; o < 256; o++) {
        float2 av = ap[(o << 8) + t];
        #pragma unroll
        for (int p = 0; p < 8; p++)
            cacc(acc[p], av, A1s[(p << 8) + o]);
    }
    #pragma unroll
    for (int p = 0; p < 8; p++)
        g_D[(((size_t)blk) << 11) + (p << 8) + t] = acc[p];
}

// J[b][i][k][p][q] = sum_x D[b][i][k][p][x] * A2[i][k][q][x]
__global__ void k_J() {
    __shared__ float2 Ds[2048], A2s[2048];
    int blk = blockIdx.x;           // 2048
    int k = blk & 15, i = (blk >> 4) & 15;
    int t = threadIdx.x;            // 64
    for (int idx = t; idx < 2048; idx += 64) {
        Ds[idx]  = g_D[(((size_t)blk) << 11) + idx];
        A2s[idx] = g_A2[((i*16 + k) << 11) + idx];
    }
    __syncthreads();
    int p = t >> 3, q = t & 7;
    float2 acc = make_float2(0.f, 0.f);
    for (int x = 0; x < 256; x++)
        cacc(acc, Ds[(p << 8) + x], A2s[(q << 8) + x]);
    g_J[blk * 64 + t] = acc;
}

// out2[b][k][p][q] = sum_i J[b][i][k][p][q] * res[i][k][p][q]
__global__ void k_out2(const float2* __restrict__ res) {
    int idx = blockIdx.x * 256 + threadIdx.x;   // 8192
    int pq = idx & 63, k = (idx >> 6) & 15, b = idx >> 10;
    float2 acc = make_float2(0.f, 0.f);
    #pragma unroll
    for (int i = 0; i < 16; i++)
        cacc(acc, g_J[(((b*16 + i)*16 + k) << 6) + pq], res[((i*16 + k) << 6) + pq]);
    g_o2[((b*16 + k) << 6) + pq] = acc;
}

// U[n][c0][c1][q][z] = sum_p out2[n][c0][p][q] * E1[c0][c1][p][z]
__global__ void k_U() {
    int idx = blockIdx.x * 256 + threadIdx.x;   // 4194304
    int z  = idx & 255;
    int q  = (idx >> 8) & 7;
    int c1 = (idx >> 11) & 15;
    int c0 = (idx >> 15) & 15;
    int n  = idx >> 19;
    float2 acc = make_float2(0.f, 0.f);
    #pragma unroll
    for (int p = 0; p < 8; p++)
        cacc(acc, g_o2[((n*16 + c0) << 6) + (p << 3) + q],
                  g_E1[((c0*16 + c1)*8 + p)*256 + z]);
    g_U[idx] = acc;
}

// x2[n][c1][z][x] = Re( sum_{c0,q} U[n][c0][c1][q][z] * E2[c0][c1][q][x] ) / 65536
__global__ void k_x2() {
    __shared__ float2 Us[16][128];
    int blk = blockIdx.x;                       // 2048
    int zg = blk & 15, c1 = (blk >> 4) & 15, n = blk >> 8;
    int z0 = zg << 4;
    int t = threadIdx.x;                        // x
    for (int idx = t; idx < 2048; idx += 256) {
        int z = idx & 15, cq = idx >> 4;
        int c0 = cq >> 3, q = cq & 7;
        Us[z][cq] = g_U[((((n*16 + c0)*16 + c1)*8 + q) << 8) + z0 + z];
    }
    __syncthreads();
    float acc[16];
    #pragma unroll
    for (int z = 0; z < 16; z++) acc[z] = 0.f;
    for (int cq = 0; cq < 128; cq++) {
        int c0 = cq >> 3, q = cq & 7;
        float2 e = g_E2[((c0*16 + c1)*8 + q)*256 + t];
        #pragma unroll
        for (int z = 0; z < 16; z++) {
            float2 u = Us[z][cq];
            acc[z] = fmaf(u.x, e.x, acc[z]);
            acc[z] = fmaf(-u.y, e.y, acc[z]);
        }
    }
    #pragma unroll
    for (int z = 0; z < 16; z++)
        g_x2[(((size_t)(n*16 + c1)) << 16) + ((z0 + z) << 8) + t] = acc[z] * (1.0f/65536.0f);
}

// u[b][hw][c] = inorm(x1+x2) + (w0 @ v + w0_b)
__global__ void k_combine(const float* __restrict__ w0w, const float* __restrict__ w0b) {
    int idx = blockIdx.x * 256 + threadIdx.x;   // b*NPIX
    int b = idx >> 16, hw = idx & 65535;
    float vv[16];
    #pragma unroll
    for (int c = 0; c < 16; c++)
        vv[c] = g_v[(((size_t)(b*16 + c)) << 16) + hw];
    float uo[16];
    #pragma unroll
    for (int c = 0; c < 16; c++) {
        size_t off = (((size_t)(b*16 + c)) << 16) + hw;
        float y = g_x1[off] + g_x2[off];
        float2 st = g_st2[b*16 + c];
        float acc = (y - st.x) * st.y + w0b[c];
        #pragma unroll
        for (int ci = 0; ci < 16; ci++)
            acc = fmaf(vv[ci], w0w[c*16 + ci], acc);
        uo[c] = acc;
    }
    float4* up = reinterpret_cast<float4*>(g_u + (((size_t)idx) << 4));
    #pragma unroll
    for (int j = 0; j < 4; j++)
        up[j] = make_float4(uo[4*j], uo[4*j+1], uo[4*j+2], uo[4*j+3]);
}

// out = (sin(u @ fc1 + b1)) @ fc2 + b2, written as [b][cout][h][w]
__global__ void k_mlp(const float* __restrict__ fc1w, const float* __restrict__ fc1b,
                      const float* __restrict__ fc2w, const float* __restrict__ fc2b,
                      float* __restrict__ out) {
    __shared__ float w1[16*128], b1[128], w2[128*3], b2s[3];
    int t = threadIdx.x;
    for (int idx = t; idx < 2048; idx += 256) w1[idx] = fc1w[idx];
    for (int idx = t; idx < 128;  idx += 256) b1[idx] = fc1b[idx];
    for (int idx = t; idx < 384;  idx += 256) w2[idx] = fc2w[idx];
    if (t < 3) b2s[t] = fc2b[t];
    __syncthreads();
    int idx = blockIdx.x * 256 + t;
    int b = idx >> 16, hw = idx & 65535;
    float ui[16];
    const float4* up = reinterpret_cast<const float4*>(g_u + (((size_t)idx) << 4));
    #pragma unroll
    for (int j = 0; j < 4; j++) {
        float4 v4 = up[j];
        ui[4*j] = v4.x; ui[4*j+1] = v4.y; ui[4*j+2] = v4.z; ui[4*j+3] = v4.w;
    }
    float o0 = b2s[0], o1 = b2s[1], o2 = b2s[2];
    for (int j = 0; j < 128; j++) {
        float pre = b1[j];
        #pragma unroll
        for (int i = 0; i < 16; i++)
            pre = fmaf(ui[i], w1[i*128 + j], pre);
        float sv = __sinf(pre);
        o0 = fmaf(sv, w2[j*3 + 0], o0);
        o1 = fmaf(sv, w2[j*3 + 1], o1);
        o2 = fmaf(sv, w2[j*3 + 2], o2);
    }
    out[(((size_t)(b*3 + 0)) << 16) + hw] = o0;
    out[(((size_t)(b*3 + 1)) << 16) + hw] = o1;
    out[(((size_t)(b*3 + 2)) << 16) + hw] = o2;
}

// ---------------- launch ----------------
extern "C" void kernel_launch(void* const* d_in, const int* in_sizes, int n_in,
                              void* d_out, int out_size) {
    (void)in_sizes; (void)n_in; (void)out_size;
    const float*  x    = (const float*) d_in[0];
    const float*  fc0w = (const float*) d_in[1];
    const float*  fc0b = (const float*) d_in[2];
    const float2* p1   = (const float2*)d_in[3];
    const float2* p2   = (const float2*)d_in[4];
    const float2* res  = (const float2*)d_in[5];
    const float*  w0w  = (const float*) d_in[6];
    const float*  w0b  = (const float*) d_in[7];
    const float*  fc1w = (const float*) d_in[8];
    const float*  fc1b = (const float*) d_in[9];
    const float*  fc2w = (const float*) d_in[10];
    const float*  fc2b = (const float*) d_in[11];
    const float*  tx   = (const float*) d_in[12];
    const float*  ty   = (const float*) d_in[13];
    float* out = (float*)d_out;

    k_fc0<<<2048, 256>>>(x, fc0w, fc0b);
    k_stats1<<<128, 256>>>();
    k_norm1<<<32768, 256>>>();

    k_fft_row_fwd<<<32768, 128>>>();           // vn -> cbuf  (FFT along w)
    k_fft_col_fwd<<<8192, 512>>>();            // cbuf -> alpha (FFT along h)

    k_small<<<2048, 256>>>(p1, p2, tx, ty);    // A1, A2, E1, E2
    k_T<<<2048, 256>>>(res);
    k_G<<<65536, 256>>>();
    k_mix<<<2048, 256>>>();                    // alpha,G -> out1

    k_fft_col_inv<<<8192, 512>>>();            // out1 -> cbuf (IFFT along h)
    k_fft_row_inv_real<<<32768, 128>>>();      // cbuf -> x1   (IFFT along w, real)

    k_D<<<2048, 256>>>();                      // alpha,A1 -> D
    k_J<<<2048, 64>>>();                       // D,A2 -> J
    k_out2<<<32, 256>>>(res);                  // J,res -> out2
    k_U<<<16384, 256>>>();                     // out2,E1 -> U
    k_x2<<<2048, 256>>>();                     // U,E2 -> x2

    k_stats2<<<128, 256>>>();                  // stats of x1+x2
    k_combine<<<2048, 256>>>(w0w, w0b);        // -> u
    k_mlp<<<2048, 256>>>(fc1w, fc1b, fc2w, fc2b, out);
}

// round 5
// speedup vs baseline: 1.0485x; 1.0485x over previous
#include <cuda_runtime.h>
#include <cstdint>

// Problem constants
#define BN   8
#define CIN  3
#define COUT 3
#define WIDC 16
#define M1C  8
#define M2C  8
#define HH   256
#define WW   256
#define NPIX 65536
#define TWO_PI 6.28318530717958647692f

typedef unsigned long long u64;

// ---------------- packed f32x2 helpers ----------------
__device__ __forceinline__ u64 pk(float x, float y) {
    u64 r; asm("mov.b64 %0, {%1,%2};" : "=l"(r) : "f"(x), "f"(y)); return r;
}
__device__ __forceinline__ float2 upk(u64 a) {
    float2 f; asm("mov.b64 {%0,%1}, %2;" : "=f"(f.x), "=f"(f.y) : "l"(a)); return f;
}
__device__ __forceinline__ u64 ffma2(u64 a, u64 b, u64 c) {
    u64 d; asm("fma.rn.f32x2 %0, %1, %2, %3;" : "=l"(d) : "l"(a), "l"(b), "l"(c)); return d;
}

// ---------------- device scratch (16B-aligned: some are read as float4) ----
__device__ __align__(16) float  g_v [BN*WIDC*NPIX];
__device__ __align__(16) float2 g_cbuf [BN*WIDC*NPIX];
__device__ __align__(16) float2 g_alpha[BN*WIDC*NPIX];
__device__ __align__(16) float2 g_out1 [BN*WIDC*NPIX];
__device__ __align__(16) float2 g_G [WIDC*WIDC*NPIX];
__device__ __align__(16) float  g_x1[BN*WIDC*NPIX];
__device__ __align__(16) float  g_x2[BN*WIDC*NPIX];
__device__ __align__(16) float  g_u [BN*NPIX*WIDC];
__device__ __align__(16) float2 g_A1[WIDC*WIDC*M1C*HH];
__device__ __align__(16) float2 g_A2[WIDC*WIDC*M2C*WW];
__device__ __align__(16) float2 g_E1[WIDC*WIDC*M1C*HH];
__device__ __align__(16) float2 g_E2[WIDC*WIDC*M2C*WW];
__device__ __align__(16) float2 g_T [WIDC*WIDC*M2C*HH];
__device__ __align__(16) float2 g_J [BN*WIDC*WIDC*M1C*M2C];
__device__ __align__(16) float2 g_o2[BN*WIDC*M1C*M2C];
__device__ __align__(16) float2 g_U [BN*WIDC*WIDC*M2C*HH];
__device__ float2 g_st1[BN*WIDC];
__device__ float2 g_st2[BN*WIDC];

// ---------------- helpers ----------------
__device__ __forceinline__ float2 cmulf(float2 a, float2 b) {
    return make_float2(fmaf(a.x, b.x, -a.y * b.y), fmaf(a.x, b.y, a.y * b.x));
}
__device__ __forceinline__ void cacc(float2& a, float2 b, float2 c) {
    a.x = fmaf(b.x, c.x, a.x); a.x = fmaf(-b.y, c.y, a.x);
    a.y = fmaf(b.x, c.y, a.y); a.y = fmaf(b.y, c.x, a.y);
}

// ---------------- 16-point register FFT (DIR=-1 fwd, +1 inv) ----------------
template<int DIR>
__device__ __forceinline__ void fft16(float2 v[16]) {
    constexpr float CC[8] = {1.f, 0.92387953251f, 0.70710678119f, 0.38268343236f,
                             0.f, -0.38268343236f, -0.70710678119f, -0.92387953251f};
    constexpr float SS[8] = {0.f, 0.38268343236f, 0.70710678119f, 0.92387953251f,
                             1.f, 0.92387953251f, 0.70710678119f, 0.38268343236f};
    #define SWP_(a,b) { float2 t_ = v[a]; v[a] = v[b]; v[b] = t_; }
    SWP_(1,8) SWP_(2,4) SWP_(3,12) SWP_(5,10) SWP_(7,14) SWP_(11,13)
    #undef SWP_
    #pragma unroll
    for (int ls = 1; ls <= 4; ls++) {
        const int len = 1 << ls, half = len >> 1, sh = 4 - ls;
        #pragma unroll
        for (int j = 0; j < 16; j += len) {
            #pragma unroll
            for (int p = 0; p < half; p++) {
                float wr = CC[p << sh];
                float wi = (float)DIR * SS[p << sh];
                float2 b = v[j + p + half];
                float2 tb = make_float2(fmaf(wr, b.x, -wi * b.y), fmaf(wr, b.y, wi * b.x));
                float2 a = v[j + p];
                v[j + p]        = make_float2(a.x + tb.x, a.y + tb.y);
                v[j + p + half] = make_float2(a.x - tb.x, a.y - tb.y);
            }
        }
    }
}

// ---------------- stage kernels ----------------

__global__ void k_fc0(const float* __restrict__ x, const float* __restrict__ fw,
                      const float* __restrict__ fb) {
    int idx = blockIdx.x * 256 + threadIdx.x;
    int b = idx >> 16, hw = idx & 65535;
    int hh = hw >> 8, ww = hw & 255;
    float xi0 = x[(size_t)(b*3 + 0)*NPIX + hw];
    float xi1 = x[(size_t)(b*3 + 1)*NPIX + hw];
    float xi2 = x[(size_t)(b*3 + 2)*NPIX + hw];
    float gx = (float)hh * (1.0f/255.0f);
    float gy = (float)ww * (1.0f/255.0f);
    #pragma unroll
    for (int c = 0; c < 16; c++) {
        float val = fb[c];
        val = fmaf(xi0, fw[c],      val);
        val = fmaf(xi1, fw[16 + c], val);
        val = fmaf(xi2, fw[32 + c], val);
        val = fmaf(gx,  fw[48 + c], val);
        val = fmaf(gy,  fw[64 + c], val);
        g_v[(((size_t)(b*16 + c)) << 16) + hw] = val;
    }
}

__device__ void stats_impl(const float* a, const float* b2, float2* st) {
    int bc = blockIdx.x;
    const float* p  = a + ((size_t)bc << 16);
    const float* p2 = b2 ? (b2 + ((size_t)bc << 16)) : nullptr;
    double s = 0.0, s2 = 0.0;
    for (int i = threadIdx.x; i < NPIX; i += 256) {
        float v = p[i];
        if (p2) v += p2[i];
        s += (double)v; s2 += (double)v * (double)v;
    }
    __shared__ double sh[256], sh2[256];
    sh[threadIdx.x] = s; sh2[threadIdx.x] = s2;
    __syncthreads();
    for (int off = 128; off; off >>= 1) {
        if (threadIdx.x < off) { sh[threadIdx.x] += sh[threadIdx.x+off]; sh2[threadIdx.x] += sh2[threadIdx.x+off]; }
        __syncthreads();
    }
    if (threadIdx.x == 0) {
        double mu  = sh[0]  / (double)NPIX;
        double var = sh2[0] / (double)NPIX - mu * mu;
        st[bc] = make_float2((float)mu, (float)(1.0 / sqrt(var + 1e-5)));
    }
}
__global__ void k_stats1() { stats_impl(g_v, nullptr, g_st1); }
__global__ void k_stats2() { stats_impl(g_x1, g_x2, g_st2); }

// forward row FFT (along w), norm fused. 8 transforms/block, 16 thr/transform.
__global__ void k_row_fwd() {
    __shared__ float2 sh[8 * 272];
    int tid = threadIdx.x;
    int r = tid >> 4, t = tid & 15;
    int row = blockIdx.x * 8 + r;               // (b*16+c)*256 + h
    float2 st = g_st1[row >> 8];
    const float* rp = g_v + (size_t)row * 256;
    float2 v[16];
    #pragma unroll
    for (int a = 0; a < 16; a++)
        v[a] = make_float2((rp[16*a + t] - st.x) * st.y, 0.f);
    fft16<-1>(v);
    float2* sb = sh + r * 272;
    #pragma unroll
    for (int c = 0; c < 16; c++) {
        float sn, cs; __sincosf(-TWO_PI * (float)(t * c) * (1.0f/256.0f), &sn, &cs);
        sb[t * 17 + c] = cmulf(make_float2(cs, sn), v[c]);
    }
    __syncthreads();
    float2 z[16];
    #pragma unroll
    for (int b = 0; b < 16; b++) z[b] = sb[b * 17 + t];
    fft16<-1>(z);
    float2* op = g_cbuf + (size_t)row * 256;
    #pragma unroll
    for (int d = 0; d < 16; d++) op[16*d + t] = z[d];
}

// inverse row FFT -> real
__global__ void k_row_inv() {
    __shared__ float2 sh[8 * 272];
    int tid = threadIdx.x;
    int r = tid >> 4, t = tid & 15;
    int row = blockIdx.x * 8 + r;
    const float2* rp = g_cbuf + (size_t)row * 256;
    float2 v[16];
    #pragma unroll
    for (int a = 0; a < 16; a++) v[a] = rp[16*a + t];
    fft16<1>(v);
    float2* sb = sh + r * 272;
    #pragma unroll
    for (int c = 0; c < 16; c++) {
        float sn, cs; __sincosf(TWO_PI * (float)(t * c) * (1.0f/256.0f), &sn, &cs);
        sb[t * 17 + c] = cmulf(make_float2(cs, sn), v[c]);
    }
    __syncthreads();
    float2 z[16];
    #pragma unroll
    for (int b = 0; b < 16; b++) z[b] = sb[b * 17 + t];
    fft16<1>(z);
    float* op = g_x1 + (size_t)row * 256;
    #pragma unroll
    for (int d = 0; d < 16; d++) op[16*d + t] = z[d].x * (1.0f/256.0f);
}

// column FFT (along h). 16 columns/block, 16 thr/transform, 256 threads.
// MODE 0: g_cbuf -> g_alpha, forward, scale 1
// MODE 1: g_out1 -> g_cbuf,  inverse, scale 1/256
template<int MODE>
__global__ void k_colfft() {
    constexpr int DIR = (MODE == 0) ? -1 : 1;
    const float scale = (MODE == 0) ? 1.0f : (1.0f/256.0f);
    const float2* __restrict__ in  = (MODE == 0) ? g_cbuf : g_out1;
    float2* __restrict__ out       = (MODE == 0) ? g_alpha : g_cbuf;
    __shared__ float2 sh[16 * 273];
    int tid = threadIdx.x;
    int t = tid >> 4, xl = tid & 15;
    int bc = blockIdx.x >> 4;
    int x0 = (blockIdx.x & 15) << 4;
    const float2* base = in + (((size_t)bc) << 16) + x0 + xl;
    float2 v[16];
    #pragma unroll
    for (int a = 0; a < 16; a++) v[a] = base[(size_t)(16*a + t) * 256];
    fft16<DIR>(v);
    float2* sb = sh + xl * 273;
    #pragma unroll
    for (int c = 0; c < 16; c++) {
        float sn, cs; __sincosf((float)DIR * TWO_PI * (float)(t * c) * (1.0f/256.0f), &sn, &cs);
        sb[t * 17 + c] = cmulf(make_float2(cs, sn), v[c]);
    }
    __syncthreads();
    float2 z[16];
    #pragma unroll
    for (int b = 0; b < 16; b++) z[b] = sb[b * 17 + t];
    fft16<DIR>(z);
    float2* ob = out + (((size_t)bc) << 16) + x0 + xl;
    #pragma unroll
    for (int d = 0; d < 16; d++) {
        float2 r = z[d];
        ob[(size_t)(t + 16*d) * 256] = make_float2(r.x * scale, r.y * scale);
    }
}

// A1/A2/E1/E2 precompute
__global__ void k_small(const float2* __restrict__ p1, const float2* __restrict__ p2,
                        const float* __restrict__ tx, const float* __restrict__ ty) {
    int idx = blockIdx.x * 256 + threadIdx.x;
    int t  = idx & 255;
    int m  = (idx >> 8) & 7;
    int ik = idx >> 11;
    float dty = ty[1] - ty[0];
    float dtx = tx[1] - tx[0];
    int fo = (t < 128) ? t : (t - 256);
    float L1 = TWO_PI * (float)fo / (256.0f * dty);
    float L2 = TWO_PI * (float)fo / (256.0f * dtx);
    float2 pv1 = p1[ik*8 + m];
    float2 pv2 = p2[ik*8 + m];
    { float ar = -pv1.x, ai = L1 - pv1.y; float d = 1.0f/(ar*ar + ai*ai);
      g_A1[idx] = make_float2(ar*d, -ai*d); }
    { float ar = -pv2.x, ai = L2 - pv2.y; float d = 1.0f/(ar*ar + ai*ai);
      g_A2[idx] = make_float2(ar*d, -ai*d); }
    { float tv = ty[t]; float e = __expf(pv1.x*tv); float sn, cs; __sincosf(pv1.y*tv, &sn, &cs);
      g_E1[idx] = make_float2(e*cs, e*sn); }
    { float tv = tx[t]; float e = __expf(pv2.x*tv); float sn, cs; __sincosf(pv2.y*tv, &sn, &cs);
      g_E2[idx] = make_float2(e*cs, e*sn); }
}

__global__ void k_T(const float2* __restrict__ res) {
    int idx = blockIdx.x * 256 + threadIdx.x;
    int o = idx & 255;
    int q = (idx >> 8) & 7;
    int ik = idx >> 11;
    float2 acc = make_float2(0.f, 0.f);
    #pragma unroll
    for (int p = 0; p < 8; p++)
        cacc(acc, res[(ik*8 + p)*8 + q], g_A1[(ik*8 + p)*256 + o]);
    g_T[idx] = acc;
}

__global__ void k_G() {
    int iko = blockIdx.x;
    int o = iko & 255, ik = iko >> 8;
    int x = threadIdx.x;
    float2 acc = make_float2(0.f, 0.f);
    #pragma unroll
    for (int q = 0; q < 8; q++)
        cacc(acc, g_T[(ik*8 + q)*256 + o], g_A2[(ik*8 + q)*256 + x]);
    g_G[(((size_t)ik) << 16) + (o << 8) + x] = acc;
}

__global__ void k_mix() {
    __shared__ float2 as_[8][16][32];
    int f0 = blockIdx.x * 32;
    int t = threadIdx.x;
    for (int idx = t; idx < 4096; idx += 256) {
        int fl = idx & 31, i = (idx >> 5) & 15, b2 = idx >> 9;
        as_[b2][i][fl] = g_alpha[(((size_t)(b2*16 + i)) << 16) + f0 + fl];
    }
    __syncthreads();
    int b = t >> 5, fl = t & 31;
    for (int k = 0; k < 16; k++) {
        float2 acc = make_float2(0.f, 0.f);
        #pragma unroll
        for (int i = 0; i < 16; i++)
            cacc(acc, as_[b][i][fl], g_G[(((size_t)(i*16 + k)) << 16) + f0 + fl]);
        g_out1[(((size_t)(b*16 + k)) << 16) + f0 + fl] = acc;
    }
}

// fused D+J with packed FFMA2.
// D[p][x] = sum_o alpha[b,i,o,x] * A1[i,k,p,o];  J[p][q] = sum_x D[p][x] * A2[i,k,q,x]
__global__ void __launch_bounds__(64) k_DJ() {
    __shared__ u64 a1v[2048], a1s[2048];   // [p][o]: {re,im}, {-im,re}
    __shared__ float2 ds[2048];            // [p][x]
    int blk = blockIdx.x;                  // ((b*16+i)*16+k)
    int k = blk & 15, i = (blk >> 4) & 15, b = blk >> 8;
    int ik = i*16 + k;
    int t = threadIdx.x;                   // 64 threads, x-tile of 4
    for (int idx = t; idx < 2048; idx += 64) {
        float2 w = g_A1[(ik << 11) + idx];
        a1v[idx] = pk(w.x, w.y);
        a1s[idx] = pk(-w.y, w.x);
    }
    __syncthreads();
    u64 acc[4][8];
    #pragma unroll
    for (int x = 0; x < 4; x++)
        #pragma unroll
        for (int p = 0; p < 8; p++) acc[x][p] = 0ull;
    const float4* ap4 = reinterpret_cast<const float4*>(g_alpha + (((size_t)(b*16 + i)) << 16));
    for (int o = 0; o < 256; o++) {
        float4 f1 = ap4[o*128 + 2*t];
        float4 f2 = ap4[o*128 + 2*t + 1];
        u64 ax[4], ay[4];
        ax[0] = pk(f1.x, f1.x); ay[0] = pk(f1.y, f1.y);
        ax[1] = pk(f1.z, f1.z); ay[1] = pk(f1.w, f1.w);
        ax[2] = pk(f2.x, f2.x); ay[2] = pk(f2.y, f2.y);
        ax[3] = pk(f2.z, f2.z); ay[3] = pk(f2.w, f2.w);
        #pragma unroll
        for (int p = 0; p < 8; p++) {
            u64 wv = a1v[(p << 8) + o];
            u64 ws = a1s[(p << 8) + o];
            #pragma unroll
            for (int x = 0; x < 4; x++) {
                acc[x][p] = ffma2(ax[x], wv, acc[x][p]);
                acc[x][p] = ffma2(ay[x], ws, acc[x][p]);
            }
        }
    }
    #pragma unroll
    for (int p = 0; p < 8; p++)
        #pragma unroll
        for (int x = 0; x < 4; x++)
            ds[(p << 8) + 4*t + x] = upk(acc[x][p]);
    __syncthreads();
    int p = t >> 3, q = t & 7;
    const float2* A2q = g_A2 + (ik << 11) + (q << 8);
    float jx = 0.f, jy = 0.f;
    for (int x = 0; x < 256; x++) {
        float2 d = ds[(p << 8) + x];
        float2 a2 = A2q[x];
        jx = fmaf(d.x, a2.x, jx); jx = fmaf(-d.y, a2.y, jx);
        jy = fmaf(d.x, a2.y, jy); jy = fmaf(d.y, a2.x, jy);
    }
    g_J[blk * 64 + t] = make_float2(jx, jy);
}

__global__ void k_out2(const float2* __restrict__ res) {
    int idx = blockIdx.x * 256 + threadIdx.x;   // 8192
    int pq = idx & 63, k = (idx >> 6) & 15, b = idx >> 10;
    float2 acc = make_float2(0.f, 0.f);
    #pragma unroll
    for (int i = 0; i < 16; i++)
        cacc(acc, g_J[(((b*16 + i)*16 + k) << 6) + pq], res[((i*16 + k) << 6) + pq]);
    g_o2[((b*16 + k) << 6) + pq] = acc;
}

__global__ void k_U() {
    int idx = blockIdx.x * 256 + threadIdx.x;   // 4194304
    int z  = idx & 255;
    int q  = (idx >> 8) & 7;
    int c1 = (idx >> 11) & 15;
    int c0 = (idx >> 15) & 15;
    int n  = idx >> 19;
    float2 acc = make_float2(0.f, 0.f);
    #pragma unroll
    for (int p = 0; p < 8; p++)
        cacc(acc, g_o2[((n*16 + c0) << 6) + (p << 3) + q],
                  g_E1[((c0*16 + c1)*8 + p)*256 + z]);
    g_U[idx] = acc;
}

// transient part with packed FFMA2. Block: (n, c1, zg of 32 z). 128 threads, x-tile 2.
__global__ void __launch_bounds__(128) k_x2() {
    __shared__ u64 usx[128 * 16], usy[128 * 16];  // [cq][zp]
    int blk = blockIdx.x;                         // ((n*16+c1)*8 + zg)
    int zg = blk & 7, c1 = (blk >> 3) & 15, n = blk >> 7;
    int z0 = zg << 5;
    int t = threadIdx.x;                          // 128
    for (int idx = t; idx < 2048; idx += 128) {
        int zp = idx & 15, cq = idx >> 4;
        int c0 = cq >> 3, q = cq & 7;
        const float2* up = g_U + (((size_t)(((n*16 + c0)*16 + c1)*8 + q)) << 8) + z0 + 2*zp;
        float2 u0 = up[0], u1 = up[1];
        usx[cq*16 + zp] = pk(u0.x, u1.x);
        usy[cq*16 + zp] = pk(-u0.y, -u1.y);
    }
    __syncthreads();
    u64 acc[2][16];
    #pragma unroll
    for (int x = 0; x < 2; x++)
        #pragma unroll
        for (int zp = 0; zp < 16; zp++) acc[x][zp] = 0ull;
    const float4* e4 = reinterpret_cast<const float4*>(g_E2);
    for (int cq = 0; cq < 128; cq++) {
        int c0 = cq >> 3, q = cq & 7;
        float4 e = e4[(((c0*16 + c1)*8 + q) << 7) + t];   // 2 float2 at x = 2t, 2t+1
        u64 ex0 = pk(e.x, e.x), ey0 = pk(e.y, e.y);
        u64 ex1 = pk(e.z, e.z), ey1 = pk(e.w, e.w);
        #pragma unroll
        for (int zp = 0; zp < 16; zp++) {
            u64 ux = usx[cq*16 + zp];
            u64 uy = usy[cq*16 + zp];
            acc[0][zp] = ffma2(ex0, ux, acc[0][zp]);
            acc[0][zp] = ffma2(ey0, uy, acc[0][zp]);
            acc[1][zp] = ffma2(ex1, ux, acc[1][zp]);
            acc[1][zp] = ffma2(ey1, uy, acc[1][zp]);
        }
    }
    float* ob = g_x2 + (((size_t)(n*16 + c1)) << 16);
    #pragma unroll
    for (int zp = 0; zp < 16; zp++) {
        float2 r0 = upk(acc[0][zp]);   // x=2t:   {z0+2zp, z0+2zp+1}
        float2 r1 = upk(acc[1][zp]);   // x=2t+1
        const float sc = 1.0f / 65536.0f;
        reinterpret_cast<float2*>(ob + (size_t)(z0 + 2*zp    ) * 256)[t] = make_float2(r0.x*sc, r1.x*sc);
        reinterpret_cast<float2*>(ob + (size_t)(z0 + 2*zp + 1) * 256)[t] = make_float2(r0.y*sc, r1.y*sc);
    }
}

__global__ void k_combine(const float* __restrict__ w0w, const float* __restrict__ w0b) {
    int idx = blockIdx.x * 256 + threadIdx.x;
    int b = idx >> 16, hw = idx & 65535;
    float vv[16];
    #pragma unroll
    for (int c = 0; c < 16; c++)
        vv[c] = g_v[(((size_t)(b*16 + c)) << 16) + hw];
    float uo[16];
    #pragma unroll
    for (int c = 0; c < 16; c++) {
        size_t off = (((size_t)(b*16 + c)) << 16) + hw;
        float y = g_x1[off] + g_x2[off];
        float2 st = g_st2[b*16 + c];
        float acc = (y - st.x) * st.y + w0b[c];
        #pragma unroll
        for (int ci = 0; ci < 16; ci++)
            acc = fmaf(vv[ci], w0w[c*16 + ci], acc);
        uo[c] = acc;
    }
    float4* up = reinterpret_cast<float4*>(g_u + (((size_t)idx) << 4));
    #pragma unroll
    for (int j = 0; j < 4; j++)
        up[j] = make_float4(uo[4*j], uo[4*j+1], uo[4*j+2], uo[4*j+3]);
}

// sin-MLP with packed FFMA2 over j-pairs
__global__ void k_mlp(const float* __restrict__ fc1w, const float* __restrict__ fc1b,
                      const float* __restrict__ fc2w, const float* __restrict__ fc2b,
                      float* __restrict__ out) {
    __shared__ u64 w1p[1024];     // [i][jp]  (pairs are adjacent in fc1w)
    __shared__ u64 b1p[64];
    __shared__ float w2s[384];
    __shared__ float b2s[3];
    int t = threadIdx.x;
    const u64* w1u = reinterpret_cast<const u64*>(fc1w);
    for (int idx = t; idx < 1024; idx += 256) w1p[idx] = w1u[idx];
    if (t < 64) b1p[t] = reinterpret_cast<const u64*>(fc1b)[t];
    for (int idx = t; idx < 384; idx += 256) w2s[idx] = fc2w[idx];
    if (t < 3) b2s[t] = fc2b[t];
    __syncthreads();
    int idx = blockIdx.x * 256 + t;
    int b = idx >> 16, hw = idx & 65535;
    float ui[16];
    const float4* up = reinterpret_cast<const float4*>(g_u + (((size_t)idx) << 4));
    #pragma unroll
    for (int j = 0; j < 4; j++) {
        float4 v4 = up[j];
        ui[4*j] = v4.x; ui[4*j+1] = v4.y; ui[4*j+2] = v4.z; ui[4*j+3] = v4.w;
    }
    u64 uip[16];
    #pragma unroll
    for (int i = 0; i < 16; i++) uip[i] = pk(ui[i], ui[i]);
    float o0 = b2s[0], o1 = b2s[1], o2 = b2s[2];
    for (int jp = 0; jp < 64; jp++) {
        u64 pre = b1p[jp];
        #pragma unroll
        for (int i = 0; i < 16; i++)
            pre = ffma2(uip[i], w1p[i*64 + jp], pre);
        float2 pf = upk(pre);
        float s0 = __sinf(pf.x), s1 = __sinf(pf.y);
        int j6 = jp * 6;
        o0 = fmaf(s0, w2s[j6 + 0], o0); o0 = fmaf(s1, w2s[j6 + 3], o0);
        o1 = fmaf(s0, w2s[j6 + 1], o1); o1 = fmaf(s1, w2s[j6 + 4], o1);
        o2 = fmaf(s0, w2s[j6 + 2], o2); o2 = fmaf(s1, w2s[j6 + 5], o2);
    }
    out[(((size_t)(b*3 + 0)) << 16) + hw] = o0;
    out[(((size_t)(b*3 + 1)) << 16) + hw] = o1;
    out[(((size_t)(b*3 + 2)) << 16) + hw] = o2;
}

// ---------------- launch ----------------
extern "C" void kernel_launch(void* const* d_in, const int* in_sizes, int n_in,
                              void* d_out, int out_size) {
    (void)in_sizes; (void)n_in; (void)out_size;
    const float*  x    = (const float*) d_in[0];
    const float*  fc0w = (const float*) d_in[1];
    const float*  fc0b = (const float*) d_in[2];
    const float2* p1   = (const float2*)d_in[3];
    const float2* p2   = (const float2*)d_in[4];
    const float2* res  = (const float2*)d_in[5];
    const float*  w0w  = (const float*) d_in[6];
    const float*  w0b  = (const float*) d_in[7];
    const float*  fc1w = (const float*) d_in[8];
    const float*  fc1b = (const float*) d_in[9];
    const float*  fc2w = (const float*) d_in[10];
    const float*  fc2b = (const float*) d_in[11];
    const float*  tx   = (const float*) d_in[12];
    const float*  ty   = (const float*) d_in[13];
    float* out = (float*)d_out;

    k_fc0<<<2048, 256>>>(x, fc0w, fc0b);
    k_stats1<<<128, 256>>>();

    k_row_fwd<<<4096, 128>>>();                // v (normed) -> cbuf
    k_colfft<0><<<2048, 256>>>();              // cbuf -> alpha (forward)

    k_small<<<2048, 256>>>(p1, p2, tx, ty);
    k_T<<<2048, 256>>>(res);
    k_G<<<65536, 256>>>();
    k_mix<<<2048, 256>>>();                    // alpha,G -> out1

    k_colfft<1><<<2048, 256>>>();              // out1 -> cbuf (inverse)
    k_row_inv<<<4096, 128>>>();                // cbuf -> x1

    k_DJ<<<2048, 64>>>();                      // alpha,A1,A2 -> J
    k_out2<<<32, 256>>>(res);
    k_U<<<16384, 256>>>();
    k_x2<<<1024, 128>>>();                     // U,E2 -> x2

    k_stats2<<<128, 256>>>();
    k_combine<<<2048, 256>>>(w0w, w0b);
    k_mlp<<<2048, 256>>>(fc1w, fc1b, fc2w, fc2b, out);
}

// round 7
// speedup vs baseline: 1.1519x; 1.0986x over previous
#include <cuda_runtime.h>
#include <cstdint>

#define BN   8
#define CIN  3
#define COUT 3
#define WIDC 16
#define M1C  8
#define M2C  8
#define HH   256
#define WW   256
#define NPIX 65536
#define TWO_PI 6.28318530717958647692f

typedef unsigned long long u64;

// ---------------- packed f32x2 helpers ----------------
__device__ __forceinline__ u64 pk(float x, float y) {
    u64 r; asm("mov.b64 %0, {%1,%2};" : "=l"(r) : "f"(x), "f"(y)); return r;
}
__device__ __forceinline__ float2 upk(u64 a) {
    float2 f; asm("mov.b64 {%0,%1}, %2;" : "=f"(f.x), "=f"(f.y) : "l"(a)); return f;
}
__device__ __forceinline__ u64 ffma2(u64 a, u64 b, u64 c) {
    u64 d; asm("fma.rn.f32x2 %0, %1, %2, %3;" : "=l"(d) : "l"(a), "l"(b), "l"(c)); return d;
}

// ---------------- device scratch ----------------
__device__ __align__(16) float  g_v [BN*WIDC*NPIX];
__device__ __align__(16) float2 g_cbuf [BN*WIDC*NPIX];
__device__ __align__(16) float2 g_alpha[BN*WIDC*NPIX];
__device__ __align__(16) float2 g_out1 [BN*WIDC*NPIX];
__device__ __align__(16) float  g_x1[BN*WIDC*NPIX];
__device__ __align__(16) float  g_x2[BN*WIDC*NPIX];
__device__ __align__(16) float2 g_A1[WIDC*WIDC*M1C*HH];
__device__ __align__(16) float2 g_A2[WIDC*WIDC*M2C*WW];
__device__ __align__(16) float2 g_E1[WIDC*WIDC*M1C*HH];
__device__ __align__(16) float2 g_E2[WIDC*WIDC*M2C*WW];
__device__ __align__(16) float2 g_T [WIDC*WIDC*M2C*HH];
__device__ __align__(16) float2 g_J [BN*WIDC*WIDC*M1C*M2C];
__device__ __align__(16) float2 g_o2[BN*WIDC*M1C*M2C];
__device__ float2 g_st1[BN*WIDC];
__device__ float2 g_st2[BN*WIDC];

// ---------------- helpers ----------------
__device__ __forceinline__ float2 cmulf(float2 a, float2 b) {
    return make_float2(fmaf(a.x, b.x, -a.y * b.y), fmaf(a.x, b.y, a.y * b.x));
}
__device__ __forceinline__ void cacc(float2& a, float2 b, float2 c) {
    a.x = fmaf(b.x, c.x, a.x); a.x = fmaf(-b.y, c.y, a.x);
    a.y = fmaf(b.x, c.y, a.y); a.y = fmaf(b.y, c.x, a.y);
}

// ---------------- 16-point register FFT ----------------
template<int DIR>
__device__ __forceinline__ void fft16(float2 v[16]) {
    constexpr float CC[8] = {1.f, 0.92387953251f, 0.70710678119f, 0.38268343236f,
                             0.f, -0.38268343236f, -0.70710678119f, -0.92387953251f};
    constexpr float SS[8] = {0.f, 0.38268343236f, 0.70710678119f, 0.92387953251f,
                             1.f, 0.92387953251f, 0.70710678119f, 0.38268343236f};
    #define SWP_(a,b) { float2 t_ = v[a]; v[a] = v[b]; v[b] = t_; }
    SWP_(1,8) SWP_(2,4) SWP_(3,12) SWP_(5,10) SWP_(7,14) SWP_(11,13)
    #undef SWP_
    #pragma unroll
    for (int ls = 1; ls <= 4; ls++) {
        const int len = 1 << ls, half = len >> 1, sh = 4 - ls;
        #pragma unroll
        for (int j = 0; j < 16; j += len) {
            #pragma unroll
            for (int p = 0; p < half; p++) {
                float wr = CC[p << sh];
                float wi = (float)DIR * SS[p << sh];
                float2 b = v[j + p + half];
                float2 tb = make_float2(fmaf(wr, b.x, -wi * b.y), fmaf(wr, b.y, wi * b.x));
                float2 a = v[j + p];
                v[j + p]        = make_float2(a.x + tb.x, a.y + tb.y);
                v[j + p + half] = make_float2(a.x - tb.x, a.y - tb.y);
            }
        }
    }
}

// ---------------- stage kernels ----------------

__global__ void k_fc0(const float* __restrict__ x, const float* __restrict__ fw,
                      const float* __restrict__ fb) {
    int idx = blockIdx.x * 256 + threadIdx.x;
    int b = idx >> 16, hw = idx & 65535;
    int hh = hw >> 8, ww = hw & 255;
    float xi0 = x[(size_t)(b*3 + 0)*NPIX + hw];
    float xi1 = x[(size_t)(b*3 + 1)*NPIX + hw];
    float xi2 = x[(size_t)(b*3 + 2)*NPIX + hw];
    float gx = (float)hh * (1.0f/255.0f);
    float gy = (float)ww * (1.0f/255.0f);
    #pragma unroll
    for (int c = 0; c < 16; c++) {
        float val = fb[c];
        val = fmaf(xi0, fw[c],      val);
        val = fmaf(xi1, fw[16 + c], val);
        val = fmaf(xi2, fw[32 + c], val);
        val = fmaf(gx,  fw[48 + c], val);
        val = fmaf(gy,  fw[64 + c], val);
        g_v[(((size_t)(b*16 + c)) << 16) + hw] = val;
    }
}

__device__ void stats_impl(const float* a, const float* b2, float2* st) {
    int bc = blockIdx.x;
    const float* p  = a + ((size_t)bc << 16);
    const float* p2 = b2 ? (b2 + ((size_t)bc << 16)) : nullptr;
    double s = 0.0, s2 = 0.0;
    for (int i = threadIdx.x; i < NPIX; i += 256) {
        float v = p[i];
        if (p2) v += p2[i];
        s += (double)v; s2 += (double)v * (double)v;
    }
    __shared__ double sh[256], sh2[256];
    sh[threadIdx.x] = s; sh2[threadIdx.x] = s2;
    __syncthreads();
    for (int off = 128; off; off >>= 1) {
        if (threadIdx.x < off) { sh[threadIdx.x] += sh[threadIdx.x+off]; sh2[threadIdx.x] += sh2[threadIdx.x+off]; }
        __syncthreads();
    }
    if (threadIdx.x == 0) {
        double mu  = sh[0]  / (double)NPIX;
        double var = sh2[0] / (double)NPIX - mu * mu;
        st[bc] = make_float2((float)mu, (float)(1.0 / sqrt(var + 1e-5)));
    }
}
__global__ void k_stats1() { stats_impl(g_v, nullptr, g_st1); }
__global__ void k_stats2() { stats_impl(g_x1, g_x2, g_st2); }

// forward row FFT (along w), norm fused
__global__ void k_row_fwd() {
    __shared__ float2 sh[8 * 272];
    int tid = threadIdx.x;
    int r = tid >> 4, t = tid & 15;
    int row = blockIdx.x * 8 + r;
    float2 st = g_st1[row >> 8];
    const float* rp = g_v + (size_t)row * 256;
    float2 v[16];
    #pragma unroll
    for (int a = 0; a < 16; a++)
        v[a] = make_float2((rp[16*a + t] - st.x) * st.y, 0.f);
    fft16<-1>(v);
    float2* sb = sh + r * 272;
    #pragma unroll
    for (int c = 0; c < 16; c++) {
        float sn, cs; __sincosf(-TWO_PI * (float)(t * c) * (1.0f/256.0f), &sn, &cs);
        sb[t * 17 + c] = cmulf(make_float2(cs, sn), v[c]);
    }
    __syncthreads();
    float2 z[16];
    #pragma unroll
    for (int b = 0; b < 16; b++) z[b] = sb[b * 17 + t];
    fft16<-1>(z);
    float2* op = g_cbuf + (size_t)row * 256;
    #pragma unroll
    for (int d = 0; d < 16; d++) op[16*d + t] = z[d];
}

// inverse row FFT -> real
__global__ void k_row_inv() {
    __shared__ float2 sh[8 * 272];
    int tid = threadIdx.x;
    int r = tid >> 4, t = tid & 15;
    int row = blockIdx.x * 8 + r;
    const float2* rp = g_cbuf + (size_t)row * 256;
    float2 v[16];
    #pragma unroll
    for (int a = 0; a < 16; a++) v[a] = rp[16*a + t];
    fft16<1>(v);
    float2* sb = sh + r * 272;
    #pragma unroll
    for (int c = 0; c < 16; c++) {
        float sn, cs; __sincosf(TWO_PI * (float)(t * c) * (1.0f/256.0f), &sn, &cs);
        sb[t * 17 + c] = cmulf(make_float2(cs, sn), v[c]);
    }
    __syncthreads();
    float2 z[16];
    #pragma unroll
    for (int b = 0; b < 16; b++) z[b] = sb[b * 17 + t];
    fft16<1>(z);
    float* op = g_x1 + (size_t)row * 256;
    #pragma unroll
    for (int d = 0; d < 16; d++) op[16*d + t] = z[d].x * (1.0f/256.0f);
}

// column FFT (along h). MODE 0: cbuf->alpha fwd; MODE 1: out1->cbuf inv /256
template<int MODE>
__global__ void k_colfft() {
    constexpr int DIR = (MODE == 0) ? -1 : 1;
    const float scale = (MODE == 0) ? 1.0f : (1.0f/256.0f);
    const float2* __restrict__ in  = (MODE == 0) ? g_cbuf : g_out1;
    float2* __restrict__ out       = (MODE == 0) ? g_alpha : g_cbuf;
    __shared__ float2 sh[16 * 273];
    int tid = threadIdx.x;
    int t = tid >> 4, xl = tid & 15;
    int bc = blockIdx.x >> 4;
    int x0 = (blockIdx.x & 15) << 4;
    const float2* base = in + (((size_t)bc) << 16) + x0 + xl;
    float2 v[16];
    #pragma unroll
    for (int a = 0; a < 16; a++) v[a] = base[(size_t)(16*a + t) * 256];
    fft16<DIR>(v);
    float2* sb = sh + xl * 273;
    #pragma unroll
    for (int c = 0; c < 16; c++) {
        float sn, cs; __sincosf((float)DIR * TWO_PI * (float)(t * c) * (1.0f/256.0f), &sn, &cs);
        sb[t * 17 + c] = cmulf(make_float2(cs, sn), v[c]);
    }
    __syncthreads();
    float2 z[16];
    #pragma unroll
    for (int b = 0; b < 16; b++) z[b] = sb[b * 17 + t];
    fft16<DIR>(z);
    float2* ob = out + (((size_t)bc) << 16) + x0 + xl;
    #pragma unroll
    for (int d = 0; d < 16; d++) {
        float2 r = z[d];
        ob[(size_t)(t + 16*d) * 256] = make_float2(r.x * scale, r.y * scale);
    }
}

// A1/A2/E1/E2 precompute
__global__ void k_small(const float2* __restrict__ p1, const float2* __restrict__ p2,
                        const float* __restrict__ tx, const float* __restrict__ ty) {
    int idx = blockIdx.x * 256 + threadIdx.x;
    int t  = idx & 255;
    int m  = (idx >> 8) & 7;
    int ik = idx >> 11;
    float dty = ty[1] - ty[0];
    float dtx = tx[1] - tx[0];
    int fo = (t < 128) ? t : (t - 256);
    float L1 = TWO_PI * (float)fo / (256.0f * dty);
    float L2 = TWO_PI * (float)fo / (256.0f * dtx);
    float2 pv1 = p1[ik*8 + m];
    float2 pv2 = p2[ik*8 + m];
    { float ar = -pv1.x, ai = L1 - pv1.y; float d = 1.0f/(ar*ar + ai*ai);
      g_A1[idx] = make_float2(ar*d, -ai*d); }
    { float ar = -pv2.x, ai = L2 - pv2.y; float d = 1.0f/(ar*ar + ai*ai);
      g_A2[idx] = make_float2(ar*d, -ai*d); }
    { float tv = ty[t]; float e = __expf(pv1.x*tv); float sn, cs; __sincosf(pv1.y*tv, &sn, &cs);
      g_E1[idx] = make_float2(e*cs, e*sn); }
    { float tv = tx[t]; float e = __expf(pv2.x*tv); float sn, cs; __sincosf(pv2.y*tv, &sn, &cs);
      g_E2[idx] = make_float2(e*cs, e*sn); }
}

__global__ void k_T(const float2* __restrict__ res) {
    int idx = blockIdx.x * 256 + threadIdx.x;
    int o = idx & 255;
    int q = (idx >> 8) & 7;
    int ik = idx >> 11;
    float2 acc = make_float2(0.f, 0.f);
    #pragma unroll
    for (int p = 0; p < 8; p++)
        cacc(acc, res[(ik*8 + p)*8 + q], g_A1[(ik*8 + p)*256 + o]);
    g_T[idx] = acc;
}

// fused G-compute + spectral mix.
// out1[b,k,f] = sum_i alpha[b,i,f] * G[i,k,f];  G[i,k,o,x] = sum_q T[ik,q,o]*A2[ik,q,x]
// block: 32-f tile => o constant, x in [x0,x0+32)
__global__ void __launch_bounds__(256) k_mixG() {
    __shared__ float2 as_[8][16][32];   // alpha tile
    __shared__ float2 Ts[256][8];       // T[ik][q] at this o
    __shared__ float2 Gs[16][32];       // per-k transfer slice
    int f0 = blockIdx.x * 32;
    int o = f0 >> 8, x0 = f0 & 255;
    int t = threadIdx.x;
    for (int idx = t; idx < 4096; idx += 256) {
        int fl = idx & 31, i = (idx >> 5) & 15, b2 = idx >> 9;
        as_[b2][i][fl] = g_alpha[(((size_t)(b2*16 + i)) << 16) + f0 + fl];
    }
    for (int idx = t; idx < 2048; idx += 256) {
        int q = idx & 7, ik = idx >> 3;
        Ts[ik][q] = g_T[(ik << 11) + (q << 8) + o];
    }
    __syncthreads();
    int b = t >> 5, fl = t & 31;
    for (int k = 0; k < 16; k++) {
        #pragma unroll
        for (int rep = 0; rep < 2; rep++) {
            int i = (t >> 5) + rep * 8;
            int ik = i*16 + k;
            float2 acc = make_float2(0.f, 0.f);
            const float2* A2b = g_A2 + (ik << 11) + x0 + fl;
            #pragma unroll
            for (int q = 0; q < 8; q++)
                cacc(acc, Ts[ik][q], A2b[q << 8]);
            Gs[i][fl] = acc;
        }
        __syncthreads();
        float2 acc = make_float2(0.f, 0.f);
        #pragma unroll
        for (int i = 0; i < 16; i++)
            cacc(acc, as_[b][i][fl], Gs[i][fl]);
        g_out1[(((size_t)(b*16 + k)) << 16) + f0 + fl] = acc;
        __syncthreads();
    }
}

// fused D+J, 256 threads, interleaved A1 (LDS.128), packed FFMA2.
__global__ void __launch_bounds__(256) k_DJ() {
    __shared__ ulonglong2 a1i[2048];   // [p][o]: {.x={re,im}, .y={-im,re}}
    __shared__ float2 ds[2048];        // [p][x]
    __shared__ float2 jred[256];
    int blk = blockIdx.x;              // ((b*16+i)*16+k), k fastest for L2 slice reuse
    int k = blk & 15, i = (blk >> 4) & 15, b = blk >> 8;
    int ik = i*16 + k;
    int t = threadIdx.x;               // x
    for (int idx = t; idx < 2048; idx += 256) {
        float2 w = g_A1[(ik << 11) + idx];
        ulonglong2 vv; vv.x = pk(w.x, w.y); vv.y = pk(-w.y, w.x);
        a1i[idx] = vv;
    }
    __syncthreads();
    u64 acc[8];
    #pragma unroll
    for (int p = 0; p < 8; p++) acc[p] = 0ull;
    const float2* ap = g_alpha + (((size_t)(b*16 + i)) << 16);
    for (int o = 0; o < 256; o++) {
        float2 av = ap[(o << 8) + t];
        u64 ax = pk(av.x, av.x), ay = pk(av.y, av.y);
        #pragma unroll
        for (int p = 0; p < 8; p++) {
            ulonglong2 w2 = a1i[(p << 8) + o];
            acc[p] = ffma2(ax, w2.x, acc[p]);
            acc[p] = ffma2(ay, w2.y, acc[p]);
        }
    }
    #pragma unroll
    for (int p = 0; p < 8; p++) ds[(p << 8) + t] = upk(acc[p]);
    __syncthreads();
    int pq = t & 63, quarter = t >> 6;
    int p = pq >> 3, q = pq & 7;
    const float2* A2q = g_A2 + (ik << 11) + (q << 8) + quarter * 64;
    const float2* dsp = ds + (p << 8) + quarter * 64;
    float jx = 0.f, jy = 0.f;
    #pragma unroll 8
    for (int x = 0; x < 64; x++) {
        float2 d = dsp[x];
        float2 a2 = A2q[x];
        jx = fmaf(d.x, a2.x, jx); jx = fmaf(-d.y, a2.y, jx);
        jy = fmaf(d.x, a2.y, jy); jy = fmaf(d.y, a2.x, jy);
    }
    jred[t] = make_float2(jx, jy);
    __syncthreads();
    if (t < 64) {
        float2 r0 = jred[t], r1 = jred[t+64], r2 = jred[t+128], r3 = jred[t+192];
        g_J[blk * 64 + t] = make_float2(r0.x+r1.x+r2.x+r3.x, r0.y+r1.y+r2.y+r3.y);
    }
}

__global__ void k_out2(const float2* __restrict__ res) {
    int idx = blockIdx.x * 256 + threadIdx.x;   // 8192
    int pq = idx & 63, k = (idx >> 6) & 15, b = idx >> 10;
    float2 acc = make_float2(0.f, 0.f);
    #pragma unroll
    for (int i = 0; i < 16; i++)
        cacc(acc, g_J[(((b*16 + i)*16 + k) << 6) + pq], res[((i*16 + k) << 6) + pq]);
    g_o2[((b*16 + k) << 6) + pq] = acc;
}

// transient part: U computed on the fly from o2+E1, then packed FFMA2 over E2.
__global__ void __launch_bounds__(128) k_x2() {
    __shared__ float2 o2s[1024];                  // o2[n][c0][p][q]
    __shared__ u64 usx[128 * 16], usy[128 * 16];  // [cq][zp]
    int blk = blockIdx.x;                         // ((n*16+c1)*8 + zg)
    int zg = blk & 7, c1 = (blk >> 3) & 15, n = blk >> 7;
    int z0 = zg << 5;
    int t = threadIdx.x;                          // 128
    for (int idx = t; idx < 1024; idx += 128)
        o2s[idx] = g_o2[(n << 10) + idx];
    __syncthreads();
    for (int idx = t; idx < 2048; idx += 128) {
        int zp = idx & 15, cq = idx >> 4;
        int c0 = cq >> 3, q = cq & 7;
        int z = z0 + 2*zp;
        float2 u0 = make_float2(0.f, 0.f), u1 = make_float2(0.f, 0.f);
        #pragma unroll
        for (int p = 0; p < 8; p++) {
            float4 e = reinterpret_cast<const float4*>(g_E1)[(((c0*16 + c1)*8 + p) << 7) + (z >> 1)];
            float2 ov = o2s[(c0 << 6) + (p << 3) + q];
            cacc(u0, ov, make_float2(e.x, e.y));
            cacc(u1, ov, make_float2(e.z, e.w));
        }
        usx[cq*16 + zp] = pk(u0.x, u1.x);
        usy[cq*16 + zp] = pk(-u0.y, -u1.y);
    }
    __syncthreads();
    u64 acc[2][16];
    #pragma unroll
    for (int x = 0; x < 2; x++)
        #pragma unroll
        for (int zp = 0; zp < 16; zp++) acc[x][zp] = 0ull;
    const float4* e4 = reinterpret_cast<const float4*>(g_E2);
    for (int cq = 0; cq < 128; cq++) {
        int c0 = cq >> 3, q = cq & 7;
        float4 e = e4[(((c0*16 + c1)*8 + q) << 7) + t];
        u64 ex0 = pk(e.x, e.x), ey0 = pk(e.y, e.y);
        u64 ex1 = pk(e.z, e.z), ey1 = pk(e.w, e.w);
        #pragma unroll
        for (int zp = 0; zp < 16; zp++) {
            u64 ux = usx[cq*16 + zp];
            u64 uy = usy[cq*16 + zp];
            acc[0][zp] = ffma2(ex0, ux, acc[0][zp]);
            acc[0][zp] = ffma2(ey0, uy, acc[0][zp]);
            acc[1][zp] = ffma2(ex1, ux, acc[1][zp]);
            acc[1][zp] = ffma2(ey1, uy, acc[1][zp]);
        }
    }
    float* ob = g_x2 + (((size_t)(n*16 + c1)) << 16);
    #pragma unroll
    for (int zp = 0; zp < 16; zp++) {
        float2 r0 = upk(acc[0][zp]);
        float2 r1 = upk(acc[1][zp]);
        const float sc = 1.0f / 65536.0f;
        reinterpret_cast<float2*>(ob + (size_t)(z0 + 2*zp    ) * 256)[t] = make_float2(r0.x*sc, r1.x*sc);
        reinterpret_cast<float2*>(ob + (size_t)(z0 + 2*zp + 1) * 256)[t] = make_float2(r0.y*sc, r1.y*sc);
    }
}

// fused: inorm(x1+x2) + 1x1-conv skip + sin-MLP -> out
__global__ void __launch_bounds__(256) k_tail(
        const float* __restrict__ w0w, const float* __restrict__ w0b,
        const float* __restrict__ fc1w, const float* __restrict__ fc1b,
        const float* __restrict__ fc2w, const float* __restrict__ fc2b,
        float* __restrict__ out) {
    __shared__ float w0s[256], w0bs[16];
    __shared__ u64 w1p[1024], b1p[64];
    __shared__ float w2s[384], b2s[3];
    int t = threadIdx.x;
    if (t < 256) w0s[t] = w0w[t];
    if (t < 16)  w0bs[t] = w0b[t];
    const u64* w1u = reinterpret_cast<const u64*>(fc1w);
    for (int idx = t; idx < 1024; idx += 256) w1p[idx] = w1u[idx];
    if (t < 64) b1p[t] = reinterpret_cast<const u64*>(fc1b)[t];
    for (int idx = t; idx < 384; idx += 256) w2s[idx] = fc2w[idx];
    if (t < 3) b2s[t] = fc2b[t];
    __syncthreads();
    int idx = blockIdx.x * 256 + t;
    int b = idx >> 16, hw = idx & 65535;
    float vv[16];
    #pragma unroll
    for (int c = 0; c < 16; c++)
        vv[c] = g_v[(((size_t)(b*16 + c)) << 16) + hw];
    u64 uip[16];
    #pragma unroll
    for (int c = 0; c < 16; c++) {
        size_t off = (((size_t)(b*16 + c)) << 16) + hw;
        float y = g_x1[off] + g_x2[off];
        float2 st = g_st2[b*16 + c];
        float acc = (y - st.x) * st.y + w0bs[c];
        #pragma unroll
        for (int ci = 0; ci < 16; ci++)
            acc = fmaf(vv[ci], w0s[c*16 + ci], acc);
        uip[c] = pk(acc, acc);
    }
    float o0 = b2s[0], o1 = b2s[1], o2 = b2s[2];
    for (int jp = 0; jp < 64; jp++) {
        u64 pre = b1p[jp];
        #pragma unroll
        for (int i = 0; i < 16; i++)
            pre = ffma2(uip[i], w1p[i*64 + jp], pre);
        float2 pf = upk(pre);
        float s0 = __sinf(pf.x), s1 = __sinf(pf.y);
        int j6 = jp * 6;
        o0 = fmaf(s0, w2s[j6 + 0], o0); o0 = fmaf(s1, w2s[j6 + 3], o0);
        o1 = fmaf(s0, w2s[j6 + 1], o1); o1 = fmaf(s1, w2s[j6 + 4], o1);
        o2 = fmaf(s0, w2s[j6 + 2], o2); o2 = fmaf(s1, w2s[j6 + 5], o2);
    }
    out[(((size_t)(b*3 + 0)) << 16) + hw] = o0;
    out[(((size_t)(b*3 + 1)) << 16) + hw] = o1;
    out[(((size_t)(b*3 + 2)) << 16) + hw] = o2;
}

// ---------------- launch ----------------
extern "C" void kernel_launch(void* const* d_in, const int* in_sizes, int n_in,
                              void* d_out, int out_size) {
    (void)in_sizes; (void)n_in; (void)out_size;
    const float*  x    = (const float*) d_in[0];
    const float*  fc0w = (const float*) d_in[1];
    const float*  fc0b = (const float*) d_in[2];
    const float2* p1   = (const float2*)d_in[3];
    const float2* p2   = (const float2*)d_in[4];
    const float2* res  = (const float2*)d_in[5];
    const float*  w0w  = (const float*) d_in[6];
    const float*  w0b  = (const float*) d_in[7];
    const float*  fc1w = (const float*) d_in[8];
    const float*  fc1b = (const float*) d_in[9];
    const float*  fc2w = (const float*) d_in[10];
    const float*  fc2b = (const float*) d_in[11];
    const float*  tx   = (const float*) d_in[12];
    const float*  ty   = (const float*) d_in[13];
    float* out = (float*)d_out;

    k_fc0<<<2048, 256>>>(x, fc0w, fc0b);
    k_stats1<<<128, 256>>>();

    k_row_fwd<<<4096, 128>>>();                // v (normed) -> cbuf
    k_colfft<0><<<2048, 256>>>();              // cbuf -> alpha

    k_small<<<2048, 256>>>(p1, p2, tx, ty);
    k_T<<<2048, 256>>>(res);
    k_mixG<<<2048, 256>>>();                   // alpha,T,A2 -> out1

    k_colfft<1><<<2048, 256>>>();              // out1 -> cbuf
    k_row_inv<<<4096, 128>>>();                // cbuf -> x1

    k_DJ<<<2048, 256>>>();                     // alpha,A1,A2 -> J
    k_out2<<<32, 256>>>(res);
    k_x2<<<1024, 128>>>();                     // o2,E1,E2 -> x2

    k_stats2<<<128, 256>>>();
    k_tail<<<2048, 256>>>(w0w, w0b, fc1w, fc1b, fc2w, fc2b, out);
}

// round 8
// speedup vs baseline: 1.3754x; 1.1941x over previous
#include <cuda_runtime.h>
#include <cstdint>

#define BN   8
#define WIDC 16
#define NPIX 65536
#define TWO_PI 6.28318530717958647692f

typedef unsigned long long u64;

// ---------------- packed f32x2 helpers ----------------
__device__ __forceinline__ u64 pk(float x, float y) {
    u64 r; asm("mov.b64 %0, {%1,%2};" : "=l"(r) : "f"(x), "f"(y)); return r;
}
__device__ __forceinline__ float2 upk(u64 a) {
    float2 f; asm("mov.b64 {%0,%1}, %2;" : "=f"(f.x), "=f"(f.y) : "l"(a)); return f;
}
__device__ __forceinline__ u64 ffma2(u64 a, u64 b, u64 c) {
    u64 d; asm("fma.rn.f32x2 %0, %1, %2, %3;" : "=l"(d) : "l"(a), "l"(b), "l"(c)); return d;
}

// ---------------- device scratch ----------------
__device__ __align__(16) float  g_v [BN*WIDC*NPIX];
__device__ __align__(16) float2 g_cbuf [BN*WIDC*NPIX];
__device__ __align__(16) float2 g_alpha[BN*WIDC*NPIX];
__device__ __align__(16) float2 g_out1 [BN*WIDC*NPIX];
__device__ __align__(16) float  g_x1[BN*WIDC*NPIX];
__device__ __align__(16) float  g_s [BN*WIDC*NPIX];   // x1+x2 combined
__device__ __align__(16) float2 g_A1[256*8*256];
__device__ __align__(16) float2 g_A2[256*8*256];
__device__ __align__(16) float2 g_E1[256*8*256];
__device__ __align__(16) float2 g_E2[256*8*256];
__device__ __align__(16) float2 g_T [256*8*256];
__device__ __align__(16) float2 g_J [BN*256*64];
__device__ __align__(16) float2 g_o2[BN*WIDC*64];
__device__ __align__(16) double2 g_sum1[BN*WIDC];
__device__ __align__(16) double2 g_sum2[BN*WIDC];
__device__ float2 g_st1[BN*WIDC];
__device__ float2 g_st2[BN*WIDC];

// ---------------- helpers ----------------
__device__ __forceinline__ float2 cmulf(float2 a, float2 b) {
    return make_float2(fmaf(a.x, b.x, -a.y * b.y), fmaf(a.x, b.y, a.y * b.x));
}
__device__ __forceinline__ void cacc(float2& a, float2 b, float2 c) {
    a.x = fmaf(b.x, c.x, a.x); a.x = fmaf(-b.y, c.y, a.x);
    a.y = fmaf(b.x, c.y, a.y); a.y = fmaf(b.y, c.x, a.y);
}

// ---------------- 16-point register FFT ----------------
template<int DIR>
__device__ __forceinline__ void fft16(float2 v[16]) {
    constexpr float CC[8] = {1.f, 0.92387953251f, 0.70710678119f, 0.38268343236f,
                             0.f, -0.38268343236f, -0.70710678119f, -0.92387953251f};
    constexpr float SS[8] = {0.f, 0.38268343236f, 0.70710678119f, 0.92387953251f,
                             1.f, 0.92387953251f, 0.70710678119f, 0.38268343236f};
    #define SWP_(a,b) { float2 t_ = v[a]; v[a] = v[b]; v[b] = t_; }
    SWP_(1,8) SWP_(2,4) SWP_(3,12) SWP_(5,10) SWP_(7,14) SWP_(11,13)
    #undef SWP_
    #pragma unroll
    for (int ls = 1; ls <= 4; ls++) {
        const int len = 1 << ls, half = len >> 1, sh = 4 - ls;
        #pragma unroll
        for (int j = 0; j < 16; j += len) {
            #pragma unroll
            for (int p = 0; p < half; p++) {
                float wr = CC[p << sh];
                float wi = (float)DIR * SS[p << sh];
                float2 b = v[j + p + half];
                float2 tb = make_float2(fmaf(wr, b.x, -wi * b.y), fmaf(wr, b.y, wi * b.x));
                float2 a = v[j + p];
                v[j + p]        = make_float2(a.x + tb.x, a.y + tb.y);
                v[j + p + half] = make_float2(a.x - tb.x, a.y - tb.y);
            }
        }
    }
}

// ---------------- stage kernels ----------------

__global__ void k_zero() {
    int t = threadIdx.x;
    if (t < 128) { g_sum1[t] = make_double2(0.0, 0.0); g_sum2[t] = make_double2(0.0, 0.0); }
}

// fc0 with fused instance-norm statistics (block partials -> double atomics)
__global__ void __launch_bounds__(256) k_fc0(const float* __restrict__ x,
                                             const float* __restrict__ fw,
                                             const float* __restrict__ fb) {
    __shared__ float2 red[16][256];
    int t = threadIdx.x;
    int idx = blockIdx.x * 256 + t;
    int b = idx >> 16, hw = idx & 65535;
    int hh = hw >> 8, ww = hw & 255;
    float xi0 = x[(size_t)(b*3 + 0)*NPIX + hw];
    float xi1 = x[(size_t)(b*3 + 1)*NPIX + hw];
    float xi2 = x[(size_t)(b*3 + 2)*NPIX + hw];
    float gx = (float)hh * (1.0f/255.0f);
    float gy = (float)ww * (1.0f/255.0f);
    #pragma unroll
    for (int c = 0; c < 16; c++) {
        float val = fb[c];
        val = fmaf(xi0, fw[c],      val);
        val = fmaf(xi1, fw[16 + c], val);
        val = fmaf(xi2, fw[32 + c], val);
        val = fmaf(gx,  fw[48 + c], val);
        val = fmaf(gy,  fw[64 + c], val);
        g_v[(((size_t)(b*16 + c)) << 16) + hw] = val;
        red[c][t] = make_float2(val, val*val);
    }
    __syncthreads();
    int c = t >> 4, j = t & 15;
    float sx = 0.f, sq = 0.f;
    #pragma unroll
    for (int kk = 0; kk < 16; kk++) { float2 r = red[c][j + kk*16]; sx += r.x; sq += r.y; }
    #pragma unroll
    for (int off = 8; off; off >>= 1) {
        sx += __shfl_down_sync(0xffffffffu, sx, off, 16);
        sq += __shfl_down_sync(0xffffffffu, sq, off, 16);
    }
    if (j == 0) {
        atomicAdd(&g_sum1[b*16 + c].x, (double)sx);
        atomicAdd(&g_sum1[b*16 + c].y, (double)sq);
    }
}

template<int WHICH>
__global__ void k_stf() {
    int t = threadIdx.x;
    if (t < 128) {
        double2 s = (WHICH == 0) ? g_sum1[t] : g_sum2[t];
        double mu  = s.x * (1.0/65536.0);
        double var = s.y * (1.0/65536.0) - mu*mu;
        float2 r = make_float2((float)mu, (float)(1.0 / sqrt(var + 1e-5)));
        if (WHICH == 0) g_st1[t] = r; else g_st2[t] = r;
    }
}

// forward row FFT (along w), norm fused
__global__ void k_row_fwd() {
    __shared__ float2 sh[8 * 272];
    int tid = threadIdx.x;
    int r = tid >> 4, t = tid & 15;
    int row = blockIdx.x * 8 + r;
    float2 st = g_st1[row >> 8];
    const float* rp = g_v + (size_t)row * 256;
    float2 v[16];
    #pragma unroll
    for (int a = 0; a < 16; a++)
        v[a] = make_float2((rp[16*a + t] - st.x) * st.y, 0.f);
    fft16<-1>(v);
    float2* sb = sh + r * 272;
    #pragma unroll
    for (int c = 0; c < 16; c++) {
        float sn, cs; __sincosf(-TWO_PI * (float)(t * c) * (1.0f/256.0f), &sn, &cs);
        sb[t * 17 + c] = cmulf(make_float2(cs, sn), v[c]);
    }
    __syncthreads();
    float2 z[16];
    #pragma unroll
    for (int b = 0; b < 16; b++) z[b] = sb[b * 17 + t];
    fft16<-1>(z);
    float2* op = g_cbuf + (size_t)row * 256;
    #pragma unroll
    for (int d = 0; d < 16; d++) op[16*d + t] = z[d];
}

// inverse row FFT -> real
__global__ void k_row_inv() {
    __shared__ float2 sh[8 * 272];
    int tid = threadIdx.x;
    int r = tid >> 4, t = tid & 15;
    int row = blockIdx.x * 8 + r;
    const float2* rp = g_cbuf + (size_t)row * 256;
    float2 v[16];
    #pragma unroll
    for (int a = 0; a < 16; a++) v[a] = rp[16*a + t];
    fft16<1>(v);
    float2* sb = sh + r * 272;
    #pragma unroll
    for (int c = 0; c < 16; c++) {
        float sn, cs; __sincosf(TWO_PI * (float)(t * c) * (1.0f/256.0f), &sn, &cs);
        sb[t * 17 + c] = cmulf(make_float2(cs, sn), v[c]);
    }
    __syncthreads();
    float2 z[16];
    #pragma unroll
    for (int b = 0; b < 16; b++) z[b] = sb[b * 17 + t];
    fft16<1>(z);
    float* op = g_x1 + (size_t)row * 256;
    #pragma unroll
    for (int d = 0; d < 16; d++) op[16*d + t] = z[d].x * (1.0f/256.0f);
}

// column FFT (along h). MODE 0: cbuf->alpha fwd; MODE 1: out1->cbuf inv /256
template<int MODE>
__global__ void k_colfft() {
    constexpr int DIR = (MODE == 0) ? -1 : 1;
    const float scale = (MODE == 0) ? 1.0f : (1.0f/256.0f);
    const float2* __restrict__ in  = (MODE == 0) ? g_cbuf : g_out1;
    float2* __restrict__ out       = (MODE == 0) ? g_alpha : g_cbuf;
    __shared__ float2 sh[16 * 273];
    int tid = threadIdx.x;
    int t = tid >> 4, xl = tid & 15;
    int bc = blockIdx.x >> 4;
    int x0 = (blockIdx.x & 15) << 4;
    const float2* base = in + (((size_t)bc) << 16) + x0 + xl;
    float2 v[16];
    #pragma unroll
    for (int a = 0; a < 16; a++) v[a] = base[(size_t)(16*a + t) * 256];
    fft16<DIR>(v);
    float2* sb = sh + xl * 273;
    #pragma unroll
    for (int c = 0; c < 16; c++) {
        float sn, cs; __sincosf((float)DIR * TWO_PI * (float)(t * c) * (1.0f/256.0f), &sn, &cs);
        sb[t * 17 + c] = cmulf(make_float2(cs, sn), v[c]);
    }
    __syncthreads();
    float2 z[16];
    #pragma unroll
    for (int b = 0; b < 16; b++) z[b] = sb[b * 17 + t];
    fft16<DIR>(z);
    float2* ob = out + (((size_t)bc) << 16) + x0 + xl;
    #pragma unroll
    for (int d = 0; d < 16; d++) {
        float2 r = z[d];
        ob[(size_t)(t + 16*d) * 256] = make_float2(r.x * scale, r.y * scale);
    }
}

// fused A1/A2/E1/E2 precompute + T contraction. One block per ik.
__global__ void __launch_bounds__(256) k_prep(const float2* __restrict__ p1,
                                              const float2* __restrict__ p2,
                                              const float2* __restrict__ res,
                                              const float* __restrict__ tx,
                                              const float* __restrict__ ty) {
    __shared__ float2 A1s[8][256];
    __shared__ float2 ress[64];
    int ik = blockIdx.x;
    int t = threadIdx.x;
    if (t < 64) ress[t] = res[ik*64 + t];
    float dty = ty[1] - ty[0];
    float dtx = tx[1] - tx[0];
    int fo = (t < 128) ? t : (t - 256);
    float L1 = TWO_PI * (float)fo / (256.0f * dty);
    float L2 = TWO_PI * (float)fo / (256.0f * dtx);
    float tyv = ty[t], txv = tx[t];
    #pragma unroll
    for (int m = 0; m < 8; m++) {
        float2 pv1 = p1[ik*8 + m];
        float2 pv2 = p2[ik*8 + m];
        int idx = (ik*8 + m)*256 + t;
        { float ar = -pv1.x, ai = L1 - pv1.y; float d = 1.0f/(ar*ar + ai*ai);
          float2 w = make_float2(ar*d, -ai*d); g_A1[idx] = w; A1s[m][t] = w; }
        { float ar = -pv2.x, ai = L2 - pv2.y; float d = 1.0f/(ar*ar + ai*ai);
          g_A2[idx] = make_float2(ar*d, -ai*d); }
        { float e = __expf(pv1.x*tyv); float sn, cs; __sincosf(pv1.y*tyv, &sn, &cs);
          g_E1[idx] = make_float2(e*cs, e*sn); }
        { float e = __expf(pv2.x*txv); float sn, cs; __sincosf(pv2.y*txv, &sn, &cs);
          g_E2[idx] = make_float2(e*cs, e*sn); }
    }
    __syncthreads();
    #pragma unroll
    for (int q = 0; q < 8; q++) {
        float2 acc = make_float2(0.f, 0.f);
        #pragma unroll
        for (int p = 0; p < 8; p++)
            cacc(acc, ress[p*8 + q], A1s[p][t]);
        g_T[(ik << 11) + (q << 8) + t] = acc;
    }
}

// fused G-compute + spectral mix
__global__ void __launch_bounds__(256) k_mixG() {
    __shared__ float2 as_[8][16][32];
    __shared__ float2 Ts[256][8];
    __shared__ float2 Gs[16][32];
    int f0 = blockIdx.x * 32;
    int o = f0 >> 8, x0 = f0 & 255;
    int t = threadIdx.x;
    for (int idx = t; idx < 4096; idx += 256) {
        int fl = idx & 31, i = (idx >> 5) & 15, b2 = idx >> 9;
        as_[b2][i][fl] = g_alpha[(((size_t)(b2*16 + i)) << 16) + f0 + fl];
    }
    for (int idx = t; idx < 2048; idx += 256) {
        int q = idx & 7, ik = idx >> 3;
        Ts[ik][q] = g_T[(ik << 11) + (q << 8) + o];
    }
    __syncthreads();
    int b = t >> 5, fl = t & 31;
    for (int k = 0; k < 16; k++) {
        #pragma unroll
        for (int rep = 0; rep < 2; rep++) {
            int i = (t >> 5) + rep * 8;
            int ik = i*16 + k;
            float2 acc = make_float2(0.f, 0.f);
            const float2* A2b = g_A2 + (ik << 11) + x0 + fl;
            #pragma unroll
            for (int q = 0; q < 8; q++)
                cacc(acc, Ts[ik][q], A2b[q << 8]);
            Gs[i][fl] = acc;
        }
        __syncthreads();
        float2 acc = make_float2(0.f, 0.f);
        #pragma unroll
        for (int i = 0; i < 16; i++)
            cacc(acc, as_[b][i][fl], Gs[i][fl]);
        g_out1[(((size_t)(b*16 + k)) << 16) + f0 + fl] = acc;
        __syncthreads();
    }
}

// fused D+J, 128 threads, 2 x per thread (float4 alpha loads), packed FFMA2.
__global__ void __launch_bounds__(128) k_DJ() {
    __shared__ ulonglong2 a1i[2048];   // [p][o]
    __shared__ float2 ds[2048];        // [p][x]
    __shared__ float2 jred[128];
    int blk = blockIdx.x;              // ((b*16+i)*16+k)
    int k = blk & 15, i = (blk >> 4) & 15, b = blk >> 8;
    int ik = i*16 + k;
    int t = threadIdx.x;               // x-pair = (2t, 2t+1)
    for (int idx = t; idx < 2048; idx += 128) {
        float2 w = g_A1[(ik << 11) + idx];
        ulonglong2 vv; vv.x = pk(w.x, w.y); vv.y = pk(-w.y, w.x);
        a1i[idx] = vv;
    }
    __syncthreads();
    u64 acc0[8], acc1[8];
    #pragma unroll
    for (int p = 0; p < 8; p++) { acc0[p] = 0ull; acc1[p] = 0ull; }
    const float4* ap4 = reinterpret_cast<const float4*>(g_alpha + (((size_t)(b*16 + i)) << 16));
    for (int o = 0; o < 256; o++) {
        float4 f = ap4[(o << 7) + t];
        u64 ax0 = pk(f.x, f.x), ay0 = pk(f.y, f.y);
        u64 ax1 = pk(f.z, f.z), ay1 = pk(f.w, f.w);
        #pragma unroll
        for (int p = 0; p < 8; p++) {
            ulonglong2 w2 = a1i[(p << 8) + o];
            acc0[p] = ffma2(ax0, w2.x, acc0[p]);
            acc0[p] = ffma2(ay0, w2.y, acc0[p]);
            acc1[p] = ffma2(ax1, w2.x, acc1[p]);
            acc1[p] = ffma2(ay1, w2.y, acc1[p]);
        }
    }
    #pragma unroll
    for (int p = 0; p < 8; p++) {
        float2 d0 = upk(acc0[p]), d1 = upk(acc1[p]);
        reinterpret_cast<float4*>(ds)[(p << 7) + t] = make_float4(d0.x, d0.y, d1.x, d1.y);
    }
    __syncthreads();
    int pq = t & 63, half = t >> 6;
    int p = pq >> 3, q = pq & 7;
    const float2* A2q = g_A2 + (ik << 11) + (q << 8) + half * 128;
    const float2* dsp = ds + (p << 8) + half * 128;
    float jx = 0.f, jy = 0.f;
    #pragma unroll 8
    for (int x = 0; x < 128; x++) {
        float2 d = dsp[x];
        float2 a2 = A2q[x];
        jx = fmaf(d.x, a2.x, jx); jx = fmaf(-d.y, a2.y, jx);
        jy = fmaf(d.x, a2.y, jy); jy = fmaf(d.y, a2.x, jy);
    }
    jred[t] = make_float2(jx, jy);
    __syncthreads();
    if (t < 64) {
        float2 r0 = jred[t], r1 = jred[t + 64];
        g_J[blk * 64 + t] = make_float2(r0.x + r1.x, r0.y + r1.y);
    }
}

__global__ void k_out2(const float2* __restrict__ res) {
    int idx = blockIdx.x * 256 + threadIdx.x;   // 8192
    int pq = idx & 63, k = (idx >> 6) & 15, b = idx >> 10;
    float2 acc = make_float2(0.f, 0.f);
    #pragma unroll
    for (int i = 0; i < 16; i++)
        cacc(acc, g_J[(((b*16 + i)*16 + k) << 6) + pq], res[((i*16 + k) << 6) + pq]);
    g_o2[((b*16 + k) << 6) + pq] = acc;
}

// transient part: U on the fly from o2+E1; adds x1; accumulates stats of s=x1+x2.
__global__ void __launch_bounds__(128) k_x2() {
    __shared__ float2 o2s[1024];
    __shared__ u64 usx[128 * 16], usy[128 * 16];
    __shared__ double rsum[128], rsq[128];
    int blk = blockIdx.x;                         // ((n*16+c1)*8 + zg)
    int zg = blk & 7, c1 = (blk >> 3) & 15, n = blk >> 7;
    int z0 = zg << 5;
    int t = threadIdx.x;                          // 128
    for (int idx = t; idx < 1024; idx += 128)
        o2s[idx] = g_o2[(n << 10) + idx];
    __syncthreads();
    for (int idx = t; idx < 2048; idx += 128) {
        int zp = idx & 15, cq = idx >> 4;
        int c0 = cq >> 3, q = cq & 7;
        int z = z0 + 2*zp;
        float2 u0 = make_float2(0.f, 0.f), u1 = make_float2(0.f, 0.f);
        #pragma unroll
        for (int p = 0; p < 8; p++) {
            float4 e = reinterpret_cast<const float4*>(g_E1)[(((c0*16 + c1)*8 + p) << 7) + (z >> 1)];
            float2 ov = o2s[(c0 << 6) + (p << 3) + q];
            cacc(u0, ov, make_float2(e.x, e.y));
            cacc(u1, ov, make_float2(e.z, e.w));
        }
        usx[cq*16 + zp] = pk(u0.x, u1.x);
        usy[cq*16 + zp] = pk(-u0.y, -u1.y);
    }
    __syncthreads();
    u64 acc[2][16];
    #pragma unroll
    for (int x = 0; x < 2; x++)
        #pragma unroll
        for (int zp = 0; zp < 16; zp++) acc[x][zp] = 0ull;
    const float4* e4 = reinterpret_cast<const float4*>(g_E2);
    for (int cq = 0; cq < 128; cq++) {
        int c0 = cq >> 3, q = cq & 7;
        float4 e = e4[(((c0*16 + c1)*8 + q) << 7) + t];
        u64 ex0 = pk(e.x, e.x), ey0 = pk(e.y, e.y);
        u64 ex1 = pk(e.z, e.z), ey1 = pk(e.w, e.w);
        #pragma unroll
        for (int zp = 0; zp < 16; zp++) {
            u64 ux = usx[cq*16 + zp];
            u64 uy = usy[cq*16 + zp];
            acc[0][zp] = ffma2(ex0, ux, acc[0][zp]);
            acc[0][zp] = ffma2(ey0, uy, acc[0][zp]);
            acc[1][zp] = ffma2(ex1, ux, acc[1][zp]);
            acc[1][zp] = ffma2(ey1, uy, acc[1][zp]);
        }
    }
    size_t plane = ((size_t)(n*16 + c1)) << 16;
    float* ob = g_s + plane;
    const float* x1p = g_x1 + plane;
    float lsum = 0.f, lsq = 0.f;
    #pragma unroll
    for (int zp = 0; zp < 16; zp++) {
        float2 r0 = upk(acc[0][zp]);   // x=2t:   rows (z0+2zp, z0+2zp+1)
        float2 r1 = upk(acc[1][zp]);   // x=2t+1
        const float sc = 1.0f / 65536.0f;
        float2 x1a = reinterpret_cast<const float2*>(x1p + (size_t)(z0 + 2*zp    ) * 256)[t];
        float2 x1b = reinterpret_cast<const float2*>(x1p + (size_t)(z0 + 2*zp + 1) * 256)[t];
        float2 va = make_float2(fmaf(r0.x, sc, x1a.x), fmaf(r1.x, sc, x1a.y));
        float2 vb = make_float2(fmaf(r0.y, sc, x1b.x), fmaf(r1.y, sc, x1b.y));
        reinterpret_cast<float2*>(ob + (size_t)(z0 + 2*zp    ) * 256)[t] = va;
        reinterpret_cast<float2*>(ob + (size_t)(z0 + 2*zp + 1) * 256)[t] = vb;
        lsum += va.x + va.y + vb.x + vb.y;
        lsq  = fmaf(va.x, va.x, lsq); lsq = fmaf(va.y, va.y, lsq);
        lsq  = fmaf(vb.x, vb.x, lsq); lsq = fmaf(vb.y, vb.y, lsq);
    }
    rsum[t] = (double)lsum; rsq[t] = (double)lsq;
    __syncthreads();
    for (int off = 64; off; off >>= 1) {
        if (t < off) { rsum[t] += rsum[t+off]; rsq[t] += rsq[t+off]; }
        __syncthreads();
    }
    if (t == 0) {
        atomicAdd(&g_sum2[n*16 + c1].x, rsum[0]);
        atomicAdd(&g_sum2[n*16 + c1].y, rsq[0]);
    }
}

// fused: inorm(s) + 1x1-conv skip + sin-MLP -> out
__global__ void __launch_bounds__(256) k_tail(
        const float* __restrict__ w0w, const float* __restrict__ w0b,
        const float* __restrict__ fc1w, const float* __restrict__ fc1b,
        const float* __restrict__ fc2w, const float* __restrict__ fc2b,
        float* __restrict__ out) {
    __shared__ float w0s[256], w0bs[16];
    __shared__ u64 w1p[1024], b1p[64];
    __shared__ float w2s[384], b2s[3];
    int t = threadIdx.x;
    if (t < 256) w0s[t] = w0w[t];
    if (t < 16)  w0bs[t] = w0b[t];
    const u64* w1u = reinterpret_cast<const u64*>(fc1w);
    for (int idx = t; idx < 1024; idx += 256) w1p[idx] = w1u[idx];
    if (t < 64) b1p[t] = reinterpret_cast<const u64*>(fc1b)[t];
    for (int idx = t; idx < 384; idx += 256) w2s[idx] = fc2w[idx];
    if (t < 3) b2s[t] = fc2b[t];
    __syncthreads();
    int idx = blockIdx.x * 256 + t;
    int b = idx >> 16, hw = idx & 65535;
    float vv[16];
    #pragma unroll
    for (int c = 0; c < 16; c++)
        vv[c] = g_v[(((size_t)(b*16 + c)) << 16) + hw];
    u64 uip[16];
    #pragma unroll
    for (int c = 0; c < 16; c++) {
        float y = g_s[(((size_t)(b*16 + c)) << 16) + hw];
        float2 st = g_st2[b*16 + c];
        float acc = (y - st.x) * st.y + w0bs[c];
        #pragma unroll
        for (int ci = 0; ci < 16; ci++)
            acc = fmaf(vv[ci], w0s[c*16 + ci], acc);
        uip[c] = pk(acc, acc);
    }
    float o0 = b2s[0], o1 = b2s[1], o2 = b2s[2];
    for (int jp = 0; jp < 64; jp++) {
        u64 pre = b1p[jp];
        #pragma unroll
        for (int i = 0; i < 16; i++)
            pre = ffma2(uip[i], w1p[i*64 + jp], pre);
        float2 pf = upk(pre);
        float s0 = __sinf(pf.x), s1 = __sinf(pf.y);
        int j6 = jp * 6;
        o0 = fmaf(s0, w2s[j6 + 0], o0); o0 = fmaf(s1, w2s[j6 + 3], o0);
        o1 = fmaf(s0, w2s[j6 + 1], o1); o1 = fmaf(s1, w2s[j6 + 4], o1);
        o2 = fmaf(s0, w2s[j6 + 2], o2); o2 = fmaf(s1, w2s[j6 + 5], o2);
    }
    out[(((size_t)(b*3 + 0)) << 16) + hw] = o0;
    out[(((size_t)(b*3 + 1)) << 16) + hw] = o1;
    out[(((size_t)(b*3 + 2)) << 16) + hw] = o2;
}

// ---------------- launch ----------------
extern "C" void kernel_launch(void* const* d_in, const int* in_sizes, int n_in,
                              void* d_out, int out_size) {
    (void)in_sizes; (void)n_in; (void)out_size;
    const float*  x    = (const float*) d_in[0];
    const float*  fc0w = (const float*) d_in[1];
    const float*  fc0b = (const float*) d_in[2];
    const float2* p1   = (const float2*)d_in[3];
    const float2* p2   = (const float2*)d_in[4];
    const float2* res  = (const float2*)d_in[5];
    const float*  w0w  = (const float*) d_in[6];
    const float*  w0b  = (const float*) d_in[7];
    const float*  fc1w = (const float*) d_in[8];
    const float*  fc1b = (const float*) d_in[9];
    const float*  fc2w = (const float*) d_in[10];
    const float*  fc2b = (const float*) d_in[11];
    const float*  tx   = (const float*) d_in[12];
    const float*  ty   = (const float*) d_in[13];
    float* out = (float*)d_out;

    k_zero<<<1, 128>>>();
    k_fc0<<<2048, 256>>>(x, fc0w, fc0b);
    k_stf<0><<<1, 128>>>();

    k_row_fwd<<<4096, 128>>>();                // v (normed) -> cbuf
    k_colfft<0><<<2048, 256>>>();              // cbuf -> alpha

    k_prep<<<256, 256>>>(p1, p2, res, tx, ty); // A1,A2,E1,E2,T
    k_mixG<<<2048, 256>>>();                   // alpha,T,A2 -> out1

    k_colfft<1><<<2048, 256>>>();              // out1 -> cbuf
    k_row_inv<<<4096, 128>>>();                // cbuf -> x1

    k_DJ<<<2048, 128>>>();                     // alpha,A1,A2 -> J
    k_out2<<<32, 256>>>(res);
    k_x2<<<1024, 128>>>();                     // o2,E1,E2,x1 -> s (+stats)
    k_stf<1><<<1, 128>>>();

    k_tail<<<2048, 256>>>(w0w, w0b, fc1w, fc1b, fc2w, fc2b, out);
}